// round 1
// baseline (speedup 1.0000x reference)
#include <cuda_runtime.h>

// Sizes: input 4096^2; level-1 subbands 2048^2, level-2 1024^2, level-3 512^2.
#define S1 2048
#define S2 1024
#define S3 512

// Scratch (static __device__ arrays — no runtime allocation).
__device__ float g_ll1[S1 * S1];
__device__ float g_lh1[S1 * S1];
__device__ float g_hl1[S1 * S1];
__device__ float g_hh1[S1 * S1];
__device__ float g_chh1[S1 * S1];
__device__ float g_rec1[S1 * S1];

__device__ float g_ll2[S2 * S2];
__device__ float g_lh2[S2 * S2];
__device__ float g_hl2[S2 * S2];
__device__ float g_hh2[S2 * S2];
__device__ float g_chh2[S2 * S2];
__device__ float g_rec2[S2 * S2];

__device__ float g_ll3[S3 * S3];
__device__ float g_lh3[S3 * S3];
__device__ float g_hl3[S3 * S3];
__device__ float g_hh3[S3 * S3];
__device__ float g_chh3[S3 * S3];

// ---------------------------------------------------------------------------
// 2D Haar DWT: src is (2*oh) x (2*ow); each thread handles 2 output columns
// (one float4 load per input row-pair, float2 stores per subband).
// ll = (a+b+c+d)/2, lh = (a+b-c-d)/2, hl = (a-b+c-d)/2, hh = (a-b-c+d)/2
// where a=src[2i][2j], b=src[2i][2j+1], c=src[2i+1][2j], d=src[2i+1][2j+1].
// ---------------------------------------------------------------------------
__global__ void dwt2_kernel(const float* __restrict__ src,
                            float* __restrict__ ll, float* __restrict__ lh,
                            float* __restrict__ hl, float* __restrict__ hh,
                            int ow, int oh)
{
    int tx = blockIdx.x * blockDim.x + threadIdx.x;  // handles out cols 2tx, 2tx+1
    int i  = blockIdx.y * blockDim.y + threadIdx.y;
    if (2 * tx >= ow || i >= oh) return;

    int W = ow * 2;
    const float4* r0 = reinterpret_cast<const float4*>(src + (size_t)(2 * i) * W);
    const float4* r1 = reinterpret_cast<const float4*>(src + (size_t)(2 * i + 1) * W);
    float4 t = r0[tx];
    float4 m = r1[tx];

    float2 vll, vlh, vhl, vhh;
    vll.x = (t.x + t.y + m.x + m.y) * 0.5f;
    vlh.x = (t.x + t.y - m.x - m.y) * 0.5f;
    vhl.x = (t.x - t.y + m.x - m.y) * 0.5f;
    vhh.x = (t.x - t.y - m.x + m.y) * 0.5f;
    vll.y = (t.z + t.w + m.z + m.w) * 0.5f;
    vlh.y = (t.z + t.w - m.z - m.w) * 0.5f;
    vhl.y = (t.z - t.w + m.z - m.w) * 0.5f;
    vhh.y = (t.z - t.w - m.z + m.w) * 0.5f;

    size_t o = (size_t)i * (ow >> 1) + tx;
    reinterpret_cast<float2*>(ll)[o] = vll;
    reinterpret_cast<float2*>(lh)[o] = vlh;
    reinterpret_cast<float2*>(hl)[o] = vhl;
    reinterpret_cast<float2*>(hh)[o] = vhh;
}

// ---------------------------------------------------------------------------
// 2D Haar IDWT: subbands are ih x iw; dst is (2*ih) x (2*iw).
// out[2i][2j]     = (ll+lh+hl+hh)/2
// out[2i][2j+1]   = (ll+lh-hl-hh)/2
// out[2i+1][2j]   = (ll-lh+hl-hh)/2
// out[2i+1][2j+1] = (ll-lh-hl+hh)/2
// Each thread handles 2 input columns -> float4 store per output row.
// ---------------------------------------------------------------------------
__global__ void idwt2_kernel(const float* __restrict__ ll, const float* __restrict__ lh,
                             const float* __restrict__ hl, const float* __restrict__ hh,
                             float* __restrict__ dst, int iw, int ih)
{
    int tx = blockIdx.x * blockDim.x + threadIdx.x;  // input cols 2tx, 2tx+1
    int i  = blockIdx.y * blockDim.y + threadIdx.y;
    if (2 * tx >= iw || i >= ih) return;

    size_t o = (size_t)i * (iw >> 1) + tx;
    float2 a = reinterpret_cast<const float2*>(ll)[o];
    float2 b = reinterpret_cast<const float2*>(lh)[o];
    float2 c = reinterpret_cast<const float2*>(hl)[o];
    float2 d = reinterpret_cast<const float2*>(hh)[o];

    int W = iw * 2;
    float4 e0, e1;
    e0.x = (a.x + b.x + c.x + d.x) * 0.5f;
    e0.y = (a.x + b.x - c.x - d.x) * 0.5f;
    e0.z = (a.y + b.y + c.y + d.y) * 0.5f;
    e0.w = (a.y + b.y - c.y - d.y) * 0.5f;
    e1.x = (a.x - b.x + c.x - d.x) * 0.5f;
    e1.y = (a.x - b.x - c.x + d.x) * 0.5f;
    e1.z = (a.y - b.y + c.y - d.y) * 0.5f;
    e1.w = (a.y - b.y - c.y + d.y) * 0.5f;

    reinterpret_cast<float4*>(dst + (size_t)(2 * i)     * W)[tx] = e0;
    reinterpret_cast<float4*>(dst + (size_t)(2 * i + 1) * W)[tx] = e1;
}

// ---------------------------------------------------------------------------
// SAME KxK cross-correlation with zero padding (matches JAX conv semantics).
// Block (32,8): 32x32 output tile; each thread computes 4 consecutive rows
// at one column. Row-sharing accumulation: (K+3)*K shared loads per thread
// instead of 4*K*K.
// n is a multiple of 32 for all call sites -> no store bounds checks.
// ---------------------------------------------------------------------------
template <int K>
__global__ void conv_kernel(const float* __restrict__ src,
                            const float* __restrict__ w,
                            const float* __restrict__ bias,
                            float* __restrict__ dst, int n)
{
    constexpr int P  = K / 2;
    constexpr int TS = 32 + K - 1;
    __shared__ float tile[TS][TS + 1];
    __shared__ float sw[K * K];

    int t = threadIdx.y * 32 + threadIdx.x;  // 0..255
    if (t < K * K) sw[t] = w[t];

    int bx = blockIdx.x * 32;
    int by = blockIdx.y * 32;

    // Cooperative halo load with zero padding.
    for (int idx = t; idx < TS * TS; idx += 256) {
        int r = idx / TS, c = idx % TS;
        int gr = by - P + r, gc = bx - P + c;
        float v = 0.0f;
        if (gr >= 0 && gr < n && gc >= 0 && gc < n)
            v = src[(size_t)gr * n + gc];
        tile[r][c] = v;
    }
    __syncthreads();

    float bv = bias[0];
    int tx   = threadIdx.x;
    int row0 = threadIdx.y * 4;  // output rows row0..row0+3 of the tile

    float acc[4] = {bv, bv, bv, bv};

#pragma unroll
    for (int u = 0; u < K + 3; u++) {
        float x[K];
#pragma unroll
        for (int v = 0; v < K; v++) x[v] = tile[row0 + u][tx + v];
#pragma unroll
        for (int r = 0; r < 4; r++) {
            int uu = u - r;
            if (uu >= 0 && uu < K) {
#pragma unroll
                for (int v = 0; v < K; v++)
                    acc[r] += x[v] * sw[uu * K + v];
            }
        }
    }

    int gc = bx + tx;
#pragma unroll
    for (int r = 0; r < 4; r++)
        dst[(size_t)(by + row0 + r) * n + gc] = acc[r];
}

// ---------------------------------------------------------------------------

static inline dim3 dwt_grid(int ow, int oh, dim3 blk)
{
    return dim3(((ow >> 1) + blk.x - 1) / blk.x, (oh + blk.y - 1) / blk.y);
}

extern "C" void kernel_launch(void* const* d_in, const int* in_sizes, int n_in,
                              void* d_out, int out_size)
{
    const float* x  = (const float*)d_in[0];
    const float* w3 = (const float*)d_in[1];
    const float* b3 = (const float*)d_in[2];
    const float* w5 = (const float*)d_in[3];
    const float* b5 = (const float*)d_in[4];
    const float* w7 = (const float*)d_in[5];
    const float* b7 = (const float*)d_in[6];
    float* out = (float*)d_out;

    float *ll1, *lh1, *hl1, *hh1, *chh1, *rec1;
    float *ll2, *lh2, *hl2, *hh2, *chh2, *rec2;
    float *ll3, *lh3, *hl3, *hh3, *chh3;
    cudaGetSymbolAddress((void**)&ll1,  g_ll1);
    cudaGetSymbolAddress((void**)&lh1,  g_lh1);
    cudaGetSymbolAddress((void**)&hl1,  g_hl1);
    cudaGetSymbolAddress((void**)&hh1,  g_hh1);
    cudaGetSymbolAddress((void**)&chh1, g_chh1);
    cudaGetSymbolAddress((void**)&rec1, g_rec1);
    cudaGetSymbolAddress((void**)&ll2,  g_ll2);
    cudaGetSymbolAddress((void**)&lh2,  g_lh2);
    cudaGetSymbolAddress((void**)&hl2,  g_hl2);
    cudaGetSymbolAddress((void**)&hh2,  g_hh2);
    cudaGetSymbolAddress((void**)&chh2, g_chh2);
    cudaGetSymbolAddress((void**)&rec2, g_rec2);
    cudaGetSymbolAddress((void**)&ll3,  g_ll3);
    cudaGetSymbolAddress((void**)&lh3,  g_lh3);
    cudaGetSymbolAddress((void**)&hl3,  g_hl3);
    cudaGetSymbolAddress((void**)&hh3,  g_hh3);
    cudaGetSymbolAddress((void**)&chh3, g_chh3);

    dim3 blk(64, 4);

    // Forward DWT, 3 levels.
    dwt2_kernel<<<dwt_grid(S1, S1, blk), blk>>>(x,   ll1, lh1, hl1, hh1, S1, S1);
    dwt2_kernel<<<dwt_grid(S2, S2, blk), blk>>>(ll1, ll2, lh2, hl2, hh2, S2, S2);
    dwt2_kernel<<<dwt_grid(S3, S3, blk), blk>>>(ll2, ll3, lh3, hl3, hh3, S3, S3);

    // Per-level HH convolutions (coarsest->3x3, mid->5x5, finest->7x7).
    {
        dim3 cblk(32, 8);
        conv_kernel<3><<<dim3(S3 / 32, S3 / 32), cblk>>>(hh3, w3, b3, chh3, S3);
        conv_kernel<5><<<dim3(S2 / 32, S2 / 32), cblk>>>(hh2, w5, b5, chh2, S2);
        conv_kernel<7><<<dim3(S1 / 32, S1 / 32), cblk>>>(hh1, w7, b7, chh1, S1);
    }

    // Inverse DWT, coarsest -> finest.
    idwt2_kernel<<<dwt_grid(S3, S3, blk), blk>>>(ll3,  lh3, hl3, chh3, rec2, S3, S3);
    idwt2_kernel<<<dwt_grid(S2, S2, blk), blk>>>(rec2, lh2, hl2, chh2, rec1, S2, S2);
    idwt2_kernel<<<dwt_grid(S1, S1, blk), blk>>>(rec1, lh1, hl1, chh1, out,  S1, S1);
}

// round 2
// speedup vs baseline: 1.2146x; 1.2146x over previous
#include <cuda_runtime.h>

#define T  64
#define HLO 8
#define IN 80      // T + 2*HLO
#define NN 4096

// Shared-memory layout (float offsets)
#define O_IN   0        // 80*80   input tile (+8 halo each side)
#define O_LL1  6400     // 40*40   lvl1 LL over [-4,36)
#define O_LH1  8000     // 32*32   lvl1 LH over [0,32)
#define O_HL1  9024     // 32*32
#define O_HH1  10048    // 38*38   lvl1 HH over [-3,35)
#define O_LL2  11492    // 20*20   lvl2 LL over [-2,18)
#define O_LH2  11892    // 16*16
#define O_HL2  12148    // 16*16
#define O_HH2  12404    // 20*20   lvl2 HH over [-2,18)
#define O_LL3  12804    // 8*8
#define O_LH3  12868    // 8*8
#define O_HL3  12932    // 8*8
#define O_HH3  12996    // 10*10   lvl3 HH over [-1,9)
#define O_CHH3 13096    // 8*8
#define O_CHH2 13160    // 16*16
#define O_CHH1 13416    // 32*32
#define O_REC2 14440    // 16*16
#define O_REC1 14696    // 32*32
#define O_W    15720    // 83: w3[9] | w5[25] | w7[49]
#define O_B    15803    // 3:  b3, b5, b7
#define SMEM_FLOATS 15808
#define SMEM_BYTES (SMEM_FLOATS * 4)

__global__ __launch_bounds__(256) void fused_wavelet_kernel(
    const float* __restrict__ x,
    const float* __restrict__ w3, const float* __restrict__ b3,
    const float* __restrict__ w5, const float* __restrict__ b5,
    const float* __restrict__ w7, const float* __restrict__ b7,
    float* __restrict__ out)
{
    extern __shared__ float s[];
    const int tid = threadIdx.x;
    const int bx = blockIdx.x, by = blockIdx.y;

    // ---- weights/biases to smem ----
    if (tid < 9)        s[O_W + tid] = w3[tid];
    else if (tid < 34)  s[O_W + tid] = w5[tid - 9];
    else if (tid < 83)  s[O_W + tid] = w7[tid - 34];
    if (tid == 83) s[O_B + 0] = b3[0];
    if (tid == 84) s[O_B + 1] = b5[0];
    if (tid == 85) s[O_B + 2] = b7[0];

    // ---- P0: load 80x80 input tile with zero-padded 8-halo ----
    {
        const int r0g = by * T - HLO;
        const int c0g = bx * T - HLO;
        for (int idx = tid; idx < IN * (IN / 4); idx += 256) {
            int r  = idx / (IN / 4);
            int c4 = idx % (IN / 4);
            int gr = r0g + r;
            int gc = c0g + c4 * 4;
            float4 v = make_float4(0.f, 0.f, 0.f, 0.f);
            if (gr >= 0 && gr < NN) {
                if (gc >= 0 && gc + 3 < NN) {
                    v = *reinterpret_cast<const float4*>(x + (size_t)gr * NN + gc);
                } else {
                    float tmp[4];
#pragma unroll
                    for (int e = 0; e < 4; e++) {
                        int gce = gc + e;
                        tmp[e] = (gce >= 0 && gce < NN) ? x[(size_t)gr * NN + gce] : 0.f;
                    }
                    v = make_float4(tmp[0], tmp[1], tmp[2], tmp[3]);
                }
            }
            *reinterpret_cast<float4*>(&s[O_IN + r * IN + c4 * 4]) = v;
        }
    }
    __syncthreads();

    // ---- P1: level-1 DWT over 40x40 positions (lvl1 coords [-4,36)) ----
    // lvl1 coeff (au-4, av-4) uses s_in rows 2au,2au+1 / cols 2av,2av+1.
    for (int idx = tid; idx < 40 * 40; idx += 256) {
        int au = idx / 40, av = idx % 40;
        float2 t0 = *reinterpret_cast<const float2*>(&s[O_IN + (2 * au) * IN + 2 * av]);
        float2 t1 = *reinterpret_cast<const float2*>(&s[O_IN + (2 * au + 1) * IN + 2 * av]);
        float ll = (t0.x + t0.y + t1.x + t1.y) * 0.5f;
        float lh = (t0.x + t0.y - t1.x - t1.y) * 0.5f;
        float hl = (t0.x - t0.y + t1.x - t1.y) * 0.5f;
        float hh = (t0.x - t0.y - t1.x + t1.y) * 0.5f;
        s[O_LL1 + au * 40 + av] = ll;
        if (au >= 1 && au < 39 && av >= 1 && av < 39)
            s[O_HH1 + (au - 1) * 38 + (av - 1)] = hh;
        if (au >= 4 && au < 36 && av >= 4 && av < 36) {
            s[O_LH1 + (au - 4) * 32 + (av - 4)] = lh;
            s[O_HL1 + (au - 4) * 32 + (av - 4)] = hl;
        }
    }
    __syncthreads();

    // ---- P2: level-2 DWT over 20x20 positions (lvl2 coords [-2,18)) ----
    for (int idx = tid; idx < 20 * 20; idx += 256) {
        int ap = idx / 20, aq = idx % 20;
        float2 t0 = *reinterpret_cast<const float2*>(&s[O_LL1 + (2 * ap) * 40 + 2 * aq]);
        float2 t1 = *reinterpret_cast<const float2*>(&s[O_LL1 + (2 * ap + 1) * 40 + 2 * aq]);
        float ll = (t0.x + t0.y + t1.x + t1.y) * 0.5f;
        float lh = (t0.x + t0.y - t1.x - t1.y) * 0.5f;
        float hl = (t0.x - t0.y + t1.x - t1.y) * 0.5f;
        float hh = (t0.x - t0.y - t1.x + t1.y) * 0.5f;
        s[O_LL2 + ap * 20 + aq] = ll;
        s[O_HH2 + ap * 20 + aq] = hh;
        if (ap >= 2 && ap < 18 && aq >= 2 && aq < 18) {
            s[O_LH2 + (ap - 2) * 16 + (aq - 2)] = lh;
            s[O_HL2 + (ap - 2) * 16 + (aq - 2)] = hl;
        }
    }
    __syncthreads();

    // ---- P3: level-3 DWT over 10x10 positions (lvl3 coords [-1,9)) ----
    if (tid < 100) {
        int as = tid / 10, at = tid % 10;
        float2 t0 = *reinterpret_cast<const float2*>(&s[O_LL2 + (2 * as) * 20 + 2 * at]);
        float2 t1 = *reinterpret_cast<const float2*>(&s[O_LL2 + (2 * as + 1) * 20 + 2 * at]);
        float ll = (t0.x + t0.y + t1.x + t1.y) * 0.5f;
        float lh = (t0.x + t0.y - t1.x - t1.y) * 0.5f;
        float hl = (t0.x - t0.y + t1.x - t1.y) * 0.5f;
        float hh = (t0.x - t0.y - t1.x + t1.y) * 0.5f;
        s[O_HH3 + as * 10 + at] = hh;
        if (as >= 1 && as < 9 && at >= 1 && at < 9) {
            s[O_LL3 + (as - 1) * 8 + (at - 1)] = ll;
            s[O_LH3 + (as - 1) * 8 + (at - 1)] = lh;
            s[O_HL3 + (as - 1) * 8 + (at - 1)] = hl;
        }
    }
    __syncthreads();

    // ---- P4: convolutions (cross-correlation, SAME zero-pad) ----
    // conv7 on HH1: 32x32 outputs, 8 row-groups x 32 cols, 4 rows/thread.
    {
        float bv = s[O_B + 2];
        float acc[4] = {bv, bv, bv, bv};
        int rg = (tid >> 5) * 4;
        int tx = tid & 31;
#pragma unroll
        for (int u = 0; u < 10; u++) {   // 7 + 4 - 1
            float xr[7];
#pragma unroll
            for (int v = 0; v < 7; v++) xr[v] = s[O_HH1 + (rg + u) * 38 + tx + v];
#pragma unroll
            for (int r = 0; r < 4; r++) {
                int uu = u - r;
                if (uu >= 0 && uu < 7) {
#pragma unroll
                    for (int v = 0; v < 7; v++)
                        acc[r] += xr[v] * s[O_W + 34 + uu * 7 + v];
                }
            }
        }
#pragma unroll
        for (int r = 0; r < 4; r++)
            s[O_CHH1 + (rg + r) * 32 + tx] = acc[r];
    }
    // conv5 on HH2: 16x16 outputs, one per thread.
    {
        int p = tid >> 4, q = tid & 15;
        float a = s[O_B + 1];
#pragma unroll
        for (int u = 0; u < 5; u++)
#pragma unroll
            for (int v = 0; v < 5; v++)
                a += s[O_HH2 + (p + u) * 20 + (q + v)] * s[O_W + 9 + u * 5 + v];
        s[O_CHH2 + p * 16 + q] = a;
    }
    // conv3 on HH3: 8x8 outputs.
    if (tid < 64) {
        int p = tid >> 3, q = tid & 7;
        float a = s[O_B + 0];
#pragma unroll
        for (int u = 0; u < 3; u++)
#pragma unroll
            for (int v = 0; v < 3; v++)
                a += s[O_HH3 + (p + u) * 10 + (q + v)] * s[O_W + u * 3 + v];
        s[O_CHH3 + p * 8 + q] = a;
    }
    __syncthreads();

    // ---- P5a: IDWT level 3 -> REC2 (16x16) ----
    if (tid < 64) {
        int i = tid >> 3, j = tid & 7;
        float a = s[O_LL3 + tid], b = s[O_LH3 + tid];
        float c = s[O_HL3 + tid], d = s[O_CHH3 + tid];
        s[O_REC2 + (2 * i) * 16 + 2 * j]         = (a + b + c + d) * 0.5f;
        s[O_REC2 + (2 * i) * 16 + 2 * j + 1]     = (a + b - c - d) * 0.5f;
        s[O_REC2 + (2 * i + 1) * 16 + 2 * j]     = (a - b + c - d) * 0.5f;
        s[O_REC2 + (2 * i + 1) * 16 + 2 * j + 1] = (a - b - c + d) * 0.5f;
    }
    __syncthreads();

    // ---- P5b: IDWT level 2 -> REC1 (32x32) ----
    {
        int i = tid >> 4, j = tid & 15;
        float a = s[O_REC2 + tid], b = s[O_LH2 + tid];
        float c = s[O_HL2 + tid], d = s[O_CHH2 + tid];
        s[O_REC1 + (2 * i) * 32 + 2 * j]         = (a + b + c + d) * 0.5f;
        s[O_REC1 + (2 * i) * 32 + 2 * j + 1]     = (a + b - c - d) * 0.5f;
        s[O_REC1 + (2 * i + 1) * 32 + 2 * j]     = (a - b + c - d) * 0.5f;
        s[O_REC1 + (2 * i + 1) * 32 + 2 * j + 1] = (a - b - c + d) * 0.5f;
    }
    __syncthreads();

    // ---- P5c: IDWT level 1 -> global output (64x64 tile) ----
    for (int idx = tid; idx < 32 * 32; idx += 256) {
        int i = idx >> 5, j = idx & 31;
        float a = s[O_REC1 + idx], b = s[O_LH1 + idx];
        float c = s[O_HL1 + idx], d = s[O_CHH1 + idx];
        float e00 = (a + b + c + d) * 0.5f;
        float e01 = (a + b - c - d) * 0.5f;
        float e10 = (a - b + c - d) * 0.5f;
        float e11 = (a - b - c + d) * 0.5f;
        int gr = by * T + 2 * i;
        int gc = bx * T + 2 * j;
        *reinterpret_cast<float2*>(out + (size_t)gr * NN + gc)       = make_float2(e00, e01);
        *reinterpret_cast<float2*>(out + (size_t)(gr + 1) * NN + gc) = make_float2(e10, e11);
    }
}

extern "C" void kernel_launch(void* const* d_in, const int* in_sizes, int n_in,
                              void* d_out, int out_size)
{
    const float* x  = (const float*)d_in[0];
    const float* w3 = (const float*)d_in[1];
    const float* b3 = (const float*)d_in[2];
    const float* w5 = (const float*)d_in[3];
    const float* b5 = (const float*)d_in[4];
    const float* w7 = (const float*)d_in[5];
    const float* b7 = (const float*)d_in[6];
    float* out = (float*)d_out;

    cudaFuncSetAttribute(fused_wavelet_kernel,
                         cudaFuncAttributeMaxDynamicSharedMemorySize, SMEM_BYTES);

    dim3 grid(NN / T, NN / T);
    fused_wavelet_kernel<<<grid, 256, SMEM_BYTES>>>(x, w3, b3, w5, b5, w7, b7, out);
}

// round 3
// speedup vs baseline: 1.5447x; 1.2718x over previous
#include <cuda_runtime.h>

#define T  64
#define NN 4096

// Shared layout (float offsets). No input staging tile: lvl1 DWT reads global.
#define O_LL1  0        // 40*40 lvl1 LL over coords [-4,36)
#define O_LH1  1600     // 32*32
#define O_HL1  2624     // 32*32
#define O_HH1  3648     // 38*38 lvl1 HH over [-3,35)
#define O_LL2  5092     // 20*20 over [-2,18)
#define O_LH2  5492     // 16*16
#define O_HL2  5748     // 16*16
#define O_HH2  6004     // 20*20 over [-2,18)
#define O_LL3  6404     // 8*8
#define O_LH3  6468     // 8*8
#define O_HL3  6532     // 8*8
#define O_HH3  6596     // 10*10 over [-1,9)
#define O_CHH3 6696     // 8*8
#define O_CHH2 6760     // 16*16
#define O_CHH1 7016     // 32*32
#define O_REC2 8040     // 16*16
#define O_REC1 8296     // 32*32
#define O_W    9320     // 83: w3[9] | w5[25] | w7[49]
#define O_B    9403     // 3
#define SMEM_FLOATS 9408
#define SMEM_BYTES (SMEM_FLOATS * 4)

__global__ __launch_bounds__(512) void fused_wavelet_kernel(
    const float* __restrict__ x,
    const float* __restrict__ w3, const float* __restrict__ b3,
    const float* __restrict__ w5, const float* __restrict__ b5,
    const float* __restrict__ w7, const float* __restrict__ b7,
    float* __restrict__ out)
{
    extern __shared__ float s[];
    const int tid = threadIdx.x;
    const int bx = blockIdx.x, by = blockIdx.y;

    // ---- weights/biases to smem ----
    if (tid < 9)        s[O_W + tid] = w3[tid];
    else if (tid < 34)  s[O_W + tid] = w5[tid - 9];
    else if (tid < 83)  s[O_W + tid] = w7[tid - 34];
    if (tid == 83) s[O_B + 0] = b3[0];
    if (tid == 84) s[O_B + 1] = b5[0];
    if (tid == 85) s[O_B + 2] = b7[0];

    // ---- P1: level-1 DWT directly from global. 40x40 quads, coords [-4,36). ----
    {
        const int r0g = by * T - 8;   // even
        const int c0g = bx * T - 8;   // even
        for (int idx = tid; idx < 1600; idx += 512) {
            int au = idx / 40, av = idx - au * 40;
            int gr = r0g + 2 * au;
            int gc = c0g + 2 * av;
            float2 t0 = make_float2(0.f, 0.f), t1 = t0;
            if ((unsigned)gr < NN && (unsigned)gc < NN) {
                const float* p = x + (size_t)gr * NN + gc;
                t0 = *reinterpret_cast<const float2*>(p);
                t1 = *reinterpret_cast<const float2*>(p + NN);
            }
            float ll = (t0.x + t0.y + t1.x + t1.y) * 0.5f;
            float lh = (t0.x + t0.y - t1.x - t1.y) * 0.5f;
            float hl = (t0.x - t0.y + t1.x - t1.y) * 0.5f;
            float hh = (t0.x - t0.y - t1.x + t1.y) * 0.5f;
            s[O_LL1 + idx] = ll;
            if (au >= 1 && au < 39 && av >= 1 && av < 39)
                s[O_HH1 + (au - 1) * 38 + (av - 1)] = hh;
            if (au >= 4 && au < 36 && av >= 4 && av < 36) {
                s[O_LH1 + (au - 4) * 32 + (av - 4)] = lh;
                s[O_HL1 + (au - 4) * 32 + (av - 4)] = hl;
            }
        }
    }
    __syncthreads();

    // ---- P2: level-2 DWT over 20x20 positions (coords [-2,18)) ----
    if (tid < 400) {
        int ap = tid / 20, aq = tid - ap * 20;
        float2 t0 = *reinterpret_cast<const float2*>(&s[O_LL1 + (2 * ap) * 40 + 2 * aq]);
        float2 t1 = *reinterpret_cast<const float2*>(&s[O_LL1 + (2 * ap + 1) * 40 + 2 * aq]);
        float ll = (t0.x + t0.y + t1.x + t1.y) * 0.5f;
        float lh = (t0.x + t0.y - t1.x - t1.y) * 0.5f;
        float hl = (t0.x - t0.y + t1.x - t1.y) * 0.5f;
        float hh = (t0.x - t0.y - t1.x + t1.y) * 0.5f;
        s[O_LL2 + tid] = ll;
        s[O_HH2 + tid] = hh;
        if (ap >= 2 && ap < 18 && aq >= 2 && aq < 18) {
            s[O_LH2 + (ap - 2) * 16 + (aq - 2)] = lh;
            s[O_HL2 + (ap - 2) * 16 + (aq - 2)] = hl;
        }
    }
    __syncthreads();

    // ---- P3: level-3 DWT over 10x10 positions (coords [-1,9)) ----
    if (tid < 100) {
        int as = tid / 10, at = tid - as * 10;
        float2 t0 = *reinterpret_cast<const float2*>(&s[O_LL2 + (2 * as) * 20 + 2 * at]);
        float2 t1 = *reinterpret_cast<const float2*>(&s[O_LL2 + (2 * as + 1) * 20 + 2 * at]);
        float ll = (t0.x + t0.y + t1.x + t1.y) * 0.5f;
        float lh = (t0.x + t0.y - t1.x - t1.y) * 0.5f;
        float hl = (t0.x - t0.y + t1.x - t1.y) * 0.5f;
        float hh = (t0.x - t0.y - t1.x + t1.y) * 0.5f;
        s[O_HH3 + tid] = hh;
        if (as >= 1 && as < 9 && at >= 1 && at < 9) {
            s[O_LL3 + (as - 1) * 8 + (at - 1)] = ll;
            s[O_LH3 + (as - 1) * 8 + (at - 1)] = lh;
            s[O_HL3 + (as - 1) * 8 + (at - 1)] = hl;
        }
    }
    __syncthreads();

    // ---- P4: convolutions. Warps 0-7: conv7. Warps 8-15: conv5 then conv3. ----
    if (tid < 256) {
        // conv7 on HH1 (38x38 incl. 3-halo) -> CHH1 32x32. 4 rows/thread.
        float bv = s[O_B + 2];
        float acc[4] = {bv, bv, bv, bv};
        int rg = (tid >> 5) * 4;
        int tx = tid & 31;
#pragma unroll
        for (int u = 0; u < 10; u++) {
            float xr[7];
#pragma unroll
            for (int v = 0; v < 7; v++) xr[v] = s[O_HH1 + (rg + u) * 38 + tx + v];
#pragma unroll
            for (int r = 0; r < 4; r++) {
                int uu = u - r;
                if (uu >= 0 && uu < 7) {
#pragma unroll
                    for (int v = 0; v < 7; v++)
                        acc[r] += xr[v] * s[O_W + 34 + uu * 7 + v];
                }
            }
        }
#pragma unroll
        for (int r = 0; r < 4; r++)
            s[O_CHH1 + (rg + r) * 32 + tx] = acc[r];
    } else {
        // conv5 on HH2 (20x20 incl. 2-halo) -> CHH2 16x16. 1 output/thread.
        int t2 = tid - 256;
        int p = t2 >> 4, q = t2 & 15;
        float a = s[O_B + 1];
#pragma unroll
        for (int u = 0; u < 5; u++)
#pragma unroll
            for (int v = 0; v < 5; v++)
                a += s[O_HH2 + (p + u) * 20 + (q + v)] * s[O_W + 9 + u * 5 + v];
        s[O_CHH2 + t2] = a;
        // conv3 on HH3 (10x10 incl. 1-halo) -> CHH3 8x8, by threads 448..511.
        if (t2 >= 192) {
            int t3 = t2 - 192;
            int pp = t3 >> 3, qq = t3 & 7;
            float a3 = s[O_B + 0];
#pragma unroll
            for (int u = 0; u < 3; u++)
#pragma unroll
                for (int v = 0; v < 3; v++)
                    a3 += s[O_HH3 + (pp + u) * 10 + (qq + v)] * s[O_W + u * 3 + v];
            s[O_CHH3 + t3] = a3;
        }
    }
    __syncthreads();

    // ---- P5a: IDWT level 3 -> REC2 (16x16) ----
    if (tid < 64) {
        int i = tid >> 3, j = tid & 7;
        float a = s[O_LL3 + tid], b = s[O_LH3 + tid];
        float c = s[O_HL3 + tid], d = s[O_CHH3 + tid];
        s[O_REC2 + (2 * i) * 16 + 2 * j]         = (a + b + c + d) * 0.5f;
        s[O_REC2 + (2 * i) * 16 + 2 * j + 1]     = (a + b - c - d) * 0.5f;
        s[O_REC2 + (2 * i + 1) * 16 + 2 * j]     = (a - b + c - d) * 0.5f;
        s[O_REC2 + (2 * i + 1) * 16 + 2 * j + 1] = (a - b - c + d) * 0.5f;
    }
    __syncthreads();

    // ---- P5b: IDWT level 2 -> REC1 (32x32) ----
    if (tid < 256) {
        int i = tid >> 4, j = tid & 15;
        float a = s[O_REC2 + tid], b = s[O_LH2 + tid];
        float c = s[O_HL2 + tid], d = s[O_CHH2 + tid];
        s[O_REC1 + (2 * i) * 32 + 2 * j]         = (a + b + c + d) * 0.5f;
        s[O_REC1 + (2 * i) * 32 + 2 * j + 1]     = (a + b - c - d) * 0.5f;
        s[O_REC1 + (2 * i + 1) * 32 + 2 * j]     = (a - b + c - d) * 0.5f;
        s[O_REC1 + (2 * i + 1) * 32 + 2 * j + 1] = (a - b - c + d) * 0.5f;
    }
    __syncthreads();

    // ---- P5c: IDWT level 1 -> global output (64x64 tile) ----
    for (int idx = tid; idx < 1024; idx += 512) {
        int i = idx >> 5, j = idx & 31;
        float a = s[O_REC1 + idx], b = s[O_LH1 + idx];
        float c = s[O_HL1 + idx], d = s[O_CHH1 + idx];
        float e00 = (a + b + c + d) * 0.5f;
        float e01 = (a + b - c - d) * 0.5f;
        float e10 = (a - b + c - d) * 0.5f;
        float e11 = (a - b - c + d) * 0.5f;
        int gr = by * T + 2 * i;
        int gc = bx * T + 2 * j;
        *reinterpret_cast<float2*>(out + (size_t)gr * NN + gc)       = make_float2(e00, e01);
        *reinterpret_cast<float2*>(out + (size_t)(gr + 1) * NN + gc) = make_float2(e10, e11);
    }
}

extern "C" void kernel_launch(void* const* d_in, const int* in_sizes, int n_in,
                              void* d_out, int out_size)
{
    const float* x  = (const float*)d_in[0];
    const float* w3 = (const float*)d_in[1];
    const float* b3 = (const float*)d_in[2];
    const float* w5 = (const float*)d_in[3];
    const float* b5 = (const float*)d_in[4];
    const float* w7 = (const float*)d_in[5];
    const float* b7 = (const float*)d_in[6];
    float* out = (float*)d_out;

    cudaFuncSetAttribute(fused_wavelet_kernel,
                         cudaFuncAttributeMaxDynamicSharedMemorySize, SMEM_BYTES);

    dim3 grid(NN / T, NN / T);
    fused_wavelet_kernel<<<grid, 512, SMEM_BYTES>>>(x, w3, b3, w5, b5, w7, b7, out);
}

// round 4
// speedup vs baseline: 1.5852x; 1.0262x over previous
#include <cuda_runtime.h>

#define T   64
#define NN  4096
#define ST1 42   // lvl1 array row stride (40 rows used)

// Shared layout (float offsets). Uniform padded subband arrays incl. halos:
// lvl1 coords [-4,36) -> 40x42, lvl2 [-2,18) -> 20x20, lvl3 [-1,9) -> 10x10.
#define O_LL1  0
#define O_LH1  1680
#define O_HL1  3360
#define O_HH1  5040
#define O_LL2  6720
#define O_LH2  7120
#define O_HL2  7520
#define O_HH2  7920
#define O_LL3  8320
#define O_LH3  8420
#define O_HL3  8520
#define O_HH3  8620
#define O_CHH2 8720    // 16x16
#define O_CHH1 8976    // 32x32
#define O_REC2 10000   // 16x16
#define O_REC1 10256   // 32x32
#define O_W    11280   // 83: w3[9] | w5[25] | w7[49]
#define O_B    11363   // 3
#define SMEM_FLOATS 11368
#define SMEM_BYTES (SMEM_FLOATS * 4)

__global__ __launch_bounds__(512) void fused_wavelet_kernel(
    const float* __restrict__ x,
    const float* __restrict__ w3, const float* __restrict__ b3,
    const float* __restrict__ w5, const float* __restrict__ b5,
    const float* __restrict__ w7, const float* __restrict__ b7,
    float* __restrict__ out)
{
    extern __shared__ float s[];
    const int tid = threadIdx.x;
    const int bx = blockIdx.x, by = blockIdx.y;

    // weights/biases -> smem
    if (tid < 9)        s[O_W + tid] = w3[tid];
    else if (tid < 34)  s[O_W + tid] = w5[tid - 9];
    else if (tid < 83)  s[O_W + tid] = w7[tid - 34];
    if (tid == 83) s[O_B + 0] = b3[0];
    if (tid == 84) s[O_B + 1] = b5[0];
    if (tid == 85) s[O_B + 2] = b7[0];

    // ---- S1: level-1 DWT straight from global. 40x20 tasks, 2 quads each. ----
    {
        const int r0g = by * T - 8;
        const int c0g = bx * T - 8;
        for (int idx = tid; idx < 800; idx += 512) {
            int au  = idx / 20;
            int avq = idx - au * 20;
            int gr = r0g + 2 * au;
            int gc = c0g + 4 * avq;
            float4 t0 = make_float4(0.f, 0.f, 0.f, 0.f), t1 = t0;
            if ((unsigned)gr < NN && (unsigned)gc <= (NN - 4)) {
                const float* p = x + (size_t)gr * NN + gc;
                t0 = *reinterpret_cast<const float4*>(p);
                t1 = *reinterpret_cast<const float4*>(p + NN);
            }
            float2 ll, lh, hl, hh;
            ll.x = (t0.x + t0.y + t1.x + t1.y) * 0.5f;
            lh.x = (t0.x + t0.y - t1.x - t1.y) * 0.5f;
            hl.x = (t0.x - t0.y + t1.x - t1.y) * 0.5f;
            hh.x = (t0.x - t0.y - t1.x + t1.y) * 0.5f;
            ll.y = (t0.z + t0.w + t1.z + t1.w) * 0.5f;
            lh.y = (t0.z + t0.w - t1.z - t1.w) * 0.5f;
            hl.y = (t0.z - t0.w + t1.z - t1.w) * 0.5f;
            hh.y = (t0.z - t0.w - t1.z + t1.w) * 0.5f;
            int base = au * ST1 + 2 * avq;
            *reinterpret_cast<float2*>(&s[O_LL1 + base]) = ll;
            *reinterpret_cast<float2*>(&s[O_LH1 + base]) = lh;
            *reinterpret_cast<float2*>(&s[O_HL1 + base]) = hl;
            *reinterpret_cast<float2*>(&s[O_HH1 + base]) = hh;
        }
    }
    __syncthreads();

    // ---- S2: level-2 DWT (400 threads, 20x20 positions) ----
    if (tid < 400) {
        int ap = tid / 20, aq = tid - ap * 20;
        float2 t0 = *reinterpret_cast<const float2*>(&s[O_LL1 + (2 * ap) * ST1 + 2 * aq]);
        float2 t1 = *reinterpret_cast<const float2*>(&s[O_LL1 + (2 * ap + 1) * ST1 + 2 * aq]);
        s[O_LL2 + tid] = (t0.x + t0.y + t1.x + t1.y) * 0.5f;
        s[O_LH2 + tid] = (t0.x + t0.y - t1.x - t1.y) * 0.5f;
        s[O_HL2 + tid] = (t0.x - t0.y + t1.x - t1.y) * 0.5f;
        s[O_HH2 + tid] = (t0.x - t0.y - t1.x + t1.y) * 0.5f;
    }
    __syncthreads();

    // ---- S3: level-3 DWT (threads 0-99) || conv5 (threads 128-383) ----
    if (tid < 100) {
        int as = tid / 10, at = tid - as * 10;
        float2 t0 = *reinterpret_cast<const float2*>(&s[O_LL2 + (2 * as) * 20 + 2 * at]);
        float2 t1 = *reinterpret_cast<const float2*>(&s[O_LL2 + (2 * as + 1) * 20 + 2 * at]);
        s[O_LL3 + tid] = (t0.x + t0.y + t1.x + t1.y) * 0.5f;
        s[O_LH3 + tid] = (t0.x + t0.y - t1.x - t1.y) * 0.5f;
        s[O_HL3 + tid] = (t0.x - t0.y + t1.x - t1.y) * 0.5f;
        s[O_HH3 + tid] = (t0.x - t0.y - t1.x + t1.y) * 0.5f;
    } else if (tid >= 128 && tid < 384) {
        // conv5 on HH2 -> CHH2 (16x16), one output per thread.
        int t2 = tid - 128;
        int p = t2 >> 4, q = t2 & 15;
        float a = s[O_B + 1];
#pragma unroll
        for (int u = 0; u < 5; u++)
#pragma unroll
            for (int v = 0; v < 5; v++)
                a += s[O_HH2 + (p + u) * 20 + (q + v)] * s[O_W + 9 + u * 5 + v];
        s[O_CHH2 + t2] = a;
    }
    __syncthreads();

    // ---- S4: conv7 on HH1 -> CHH1 (32x32). All 512 threads, 2 rows each.
    //      Weight-row rotation: each weight row loaded once, reused for acc1. ----
    {
        int rp = tid >> 5;     // 0..15 -> output rows 2rp, 2rp+1
        int tx = tid & 31;
        float bv = s[O_B + 2];
        float acc0 = bv, acc1 = bv;
        float wprev[7];
#pragma unroll
        for (int u = 0; u < 8; u++) {
            float xr[7], wcur[7];
            const float* row = &s[O_HH1 + (2 * rp + 1 + u) * ST1 + tx + 1];
#pragma unroll
            for (int v = 0; v < 7; v++) xr[v] = row[v];
            if (u < 7) {
#pragma unroll
                for (int v = 0; v < 7; v++) wcur[v] = s[O_W + 34 + u * 7 + v];
#pragma unroll
                for (int v = 0; v < 7; v++) acc0 += xr[v] * wcur[v];
            }
            if (u >= 1) {
#pragma unroll
                for (int v = 0; v < 7; v++) acc1 += xr[v] * wprev[v];
            }
#pragma unroll
            for (int v = 0; v < 7; v++) wprev[v] = wcur[v];
        }
        s[O_CHH1 + (2 * rp) * 32 + tx]     = acc0;
        s[O_CHH1 + (2 * rp + 1) * 32 + tx] = acc1;
    }
    __syncthreads();

    // ---- S5: IDWT level 3 with inline conv3 (64 threads) -> REC2 (16x16) ----
    if (tid < 64) {
        int i = tid >> 3, j = tid & 7;
        float d = s[O_B + 0];
#pragma unroll
        for (int u = 0; u < 3; u++)
#pragma unroll
            for (int v = 0; v < 3; v++)
                d += s[O_HH3 + (i + u) * 10 + (j + v)] * s[O_W + u * 3 + v];
        float a = s[O_LL3 + (i + 1) * 10 + (j + 1)];
        float b = s[O_LH3 + (i + 1) * 10 + (j + 1)];
        float c = s[O_HL3 + (i + 1) * 10 + (j + 1)];
        *reinterpret_cast<float2*>(&s[O_REC2 + (2 * i) * 16 + 2 * j]) =
            make_float2((a + b + c + d) * 0.5f, (a + b - c - d) * 0.5f);
        *reinterpret_cast<float2*>(&s[O_REC2 + (2 * i + 1) * 16 + 2 * j]) =
            make_float2((a - b + c - d) * 0.5f, (a - b - c + d) * 0.5f);
    }
    __syncthreads();

    // ---- S6: IDWT level 2 (256 threads) -> REC1 (32x32) ----
    if (tid < 256) {
        int i = tid >> 4, j = tid & 15;
        float a = s[O_REC2 + tid];
        float b = s[O_LH2 + (i + 2) * 20 + (j + 2)];
        float c = s[O_HL2 + (i + 2) * 20 + (j + 2)];
        float d = s[O_CHH2 + tid];
        *reinterpret_cast<float2*>(&s[O_REC1 + (2 * i) * 32 + 2 * j]) =
            make_float2((a + b + c + d) * 0.5f, (a + b - c - d) * 0.5f);
        *reinterpret_cast<float2*>(&s[O_REC1 + (2 * i + 1) * 32 + 2 * j]) =
            make_float2((a - b + c - d) * 0.5f, (a - b - c + d) * 0.5f);
    }
    __syncthreads();

    // ---- S7: IDWT level 1 -> global output. 512 threads, 2 quads each, float4 stores. ----
    {
        int i  = tid >> 4;    // 0..31
        int jq = tid & 15;    // handles cols j = 2jq, 2jq+1
        float2 a = *reinterpret_cast<const float2*>(&s[O_REC1 + i * 32 + 2 * jq]);
        float2 b = *reinterpret_cast<const float2*>(&s[O_LH1 + (i + 4) * ST1 + 2 * jq + 4]);
        float2 c = *reinterpret_cast<const float2*>(&s[O_HL1 + (i + 4) * ST1 + 2 * jq + 4]);
        float2 d = *reinterpret_cast<const float2*>(&s[O_CHH1 + i * 32 + 2 * jq]);
        float4 e0, e1;
        e0.x = (a.x + b.x + c.x + d.x) * 0.5f;
        e0.y = (a.x + b.x - c.x - d.x) * 0.5f;
        e0.z = (a.y + b.y + c.y + d.y) * 0.5f;
        e0.w = (a.y + b.y - c.y - d.y) * 0.5f;
        e1.x = (a.x - b.x + c.x - d.x) * 0.5f;
        e1.y = (a.x - b.x - c.x + d.x) * 0.5f;
        e1.z = (a.y - b.y + c.y - d.y) * 0.5f;
        e1.w = (a.y - b.y - c.y + d.y) * 0.5f;
        int gr = by * T + 2 * i;
        int gc = bx * T + 4 * jq;
        *reinterpret_cast<float4*>(out + (size_t)gr * NN + gc)       = e0;
        *reinterpret_cast<float4*>(out + (size_t)(gr + 1) * NN + gc) = e1;
    }
}

extern "C" void kernel_launch(void* const* d_in, const int* in_sizes, int n_in,
                              void* d_out, int out_size)
{
    const float* x  = (const float*)d_in[0];
    const float* w3 = (const float*)d_in[1];
    const float* b3 = (const float*)d_in[2];
    const float* w5 = (const float*)d_in[3];
    const float* b5 = (const float*)d_in[4];
    const float* w7 = (const float*)d_in[5];
    const float* b7 = (const float*)d_in[6];
    float* out = (float*)d_out;

    cudaFuncSetAttribute(fused_wavelet_kernel,
                         cudaFuncAttributeMaxDynamicSharedMemorySize, SMEM_BYTES);

    dim3 grid(NN / T, NN / T);
    fused_wavelet_kernel<<<grid, 512, SMEM_BYTES>>>(x, w3, b3, w5, b5, w7, b7, out);
}

// round 5
// speedup vs baseline: 1.6585x; 1.0463x over previous
#include <cuda_runtime.h>

#define T   64
#define NN  4096
#define ST1 42   // lvl1 array row stride (40 rows used, coords [-4,36))

// Shared layout (float offsets).
#define O_LH1  0        // 40x42
#define O_HL1  1680
#define O_HH1  3360
#define O_LL2  5040     // 20x20, coords [-2,18)
#define O_LH2  5440
#define O_HL2  5840
#define O_HH2  6240
#define O_LL3  6640     // 10x10, coords [-1,9)
#define O_LH3  6740
#define O_HL3  6840
#define O_HH3  6940
#define O_CHH2 7040     // 16x16
#define O_CHH1 7296     // 32x32
#define O_REC2 8320     // 16x16
#define SMEM_FLOATS 8576

__constant__ float c_w3[9];
__constant__ float c_w5[25];
__constant__ float c_w7[49];
__constant__ float c_b3[1];
__constant__ float c_b5[1];
__constant__ float c_b7[1];

__global__ __launch_bounds__(512) void fused_wavelet_kernel(
    const float* __restrict__ x, float* __restrict__ out)
{
    __shared__ float s[SMEM_FLOATS];
    const int tid = threadIdx.x;
    const int bx = blockIdx.x, by = blockIdx.y;

    // ---- S1: fused level-1 + level-2 DWT. 400 threads; each owns one lvl2
    //      position = 2x2 lvl1 quads = 4x4 input pixels (4 x float4 from gmem).
    if (tid < 400) {
        int ap = tid / 20, aq = tid - ap * 20;
        int gr = by * T - 8 + 4 * ap;     // 4-aligned group; all-in or all-out
        int gc = bx * T - 8 + 4 * aq;
        float4 A = make_float4(0.f, 0.f, 0.f, 0.f), B = A, C = A, D = A;
        if ((unsigned)gr < NN && (unsigned)gc < NN) {
            const float* p = x + (size_t)gr * NN + gc;
            A = *reinterpret_cast<const float4*>(p);
            B = *reinterpret_cast<const float4*>(p + NN);
            C = *reinterpret_cast<const float4*>(p + 2 * NN);
            D = *reinterpret_cast<const float4*>(p + 3 * NN);
        }
        // lvl1 butterflies (quads 00,01,10,11)
        float ll00 = (A.x + A.y + B.x + B.y) * 0.5f;
        float lh00 = (A.x + A.y - B.x - B.y) * 0.5f;
        float hl00 = (A.x - A.y + B.x - B.y) * 0.5f;
        float hh00 = (A.x - A.y - B.x + B.y) * 0.5f;
        float ll01 = (A.z + A.w + B.z + B.w) * 0.5f;
        float lh01 = (A.z + A.w - B.z - B.w) * 0.5f;
        float hl01 = (A.z - A.w + B.z - B.w) * 0.5f;
        float hh01 = (A.z - A.w - B.z + B.w) * 0.5f;
        float ll10 = (C.x + C.y + D.x + D.y) * 0.5f;
        float lh10 = (C.x + C.y - D.x - D.y) * 0.5f;
        float hl10 = (C.x - C.y + D.x - D.y) * 0.5f;
        float hh10 = (C.x - C.y - D.x + D.y) * 0.5f;
        float ll11 = (C.z + C.w + D.z + D.w) * 0.5f;
        float lh11 = (C.z + C.w - D.z - D.w) * 0.5f;
        float hl11 = (C.z - C.w + D.z - D.w) * 0.5f;
        float hh11 = (C.z - C.w - D.z + D.w) * 0.5f;

        int r0 = (2 * ap) * ST1 + 2 * aq;
        int r1 = r0 + ST1;
        *reinterpret_cast<float2*>(&s[O_LH1 + r0]) = make_float2(lh00, lh01);
        *reinterpret_cast<float2*>(&s[O_LH1 + r1]) = make_float2(lh10, lh11);
        *reinterpret_cast<float2*>(&s[O_HL1 + r0]) = make_float2(hl00, hl01);
        *reinterpret_cast<float2*>(&s[O_HL1 + r1]) = make_float2(hl10, hl11);
        *reinterpret_cast<float2*>(&s[O_HH1 + r0]) = make_float2(hh00, hh01);
        *reinterpret_cast<float2*>(&s[O_HH1 + r1]) = make_float2(hh10, hh11);

        // lvl2 butterfly from the four lvl1 LLs
        s[O_LL2 + tid] = (ll00 + ll01 + ll10 + ll11) * 0.5f;
        s[O_LH2 + tid] = (ll00 + ll01 - ll10 - ll11) * 0.5f;
        s[O_HL2 + tid] = (ll00 - ll01 + ll10 - ll11) * 0.5f;
        s[O_HH2 + tid] = (ll00 - ll01 - ll10 + ll11) * 0.5f;
    }
    __syncthreads();

    // ---- S2: level-3 DWT (tid<100) || conv5 (tid>=256) ----
    if (tid < 100) {
        int as = tid / 10, at = tid - as * 10;
        float2 t0 = *reinterpret_cast<const float2*>(&s[O_LL2 + (2 * as) * 20 + 2 * at]);
        float2 t1 = *reinterpret_cast<const float2*>(&s[O_LL2 + (2 * as + 1) * 20 + 2 * at]);
        s[O_LL3 + tid] = (t0.x + t0.y + t1.x + t1.y) * 0.5f;
        s[O_LH3 + tid] = (t0.x + t0.y - t1.x - t1.y) * 0.5f;
        s[O_HL3 + tid] = (t0.x - t0.y + t1.x - t1.y) * 0.5f;
        s[O_HH3 + tid] = (t0.x - t0.y - t1.x + t1.y) * 0.5f;
    } else if (tid >= 256) {
        // conv5 on HH2 -> CHH2 (16x16), one output per thread.
        int t2 = tid - 256;
        int p = t2 >> 4, q = t2 & 15;
        float a = c_b5[0];
#pragma unroll
        for (int u = 0; u < 5; u++)
#pragma unroll
            for (int v = 0; v < 5; v++)
                a += s[O_HH2 + (p + u) * 20 + (q + v)] * c_w5[u * 5 + v];
        s[O_CHH2 + t2] = a;
    }
    __syncthreads();

    // ---- S3: conv7 on HH1 -> CHH1 (all 512, 2 rows each);
    //      warps 14-15 additionally do IDWT3 + inline conv3 -> REC2. ----
    {
        int rp = tid >> 5;
        int tx = tid & 31;
        float bv = c_b7[0];
        float acc0 = bv, acc1 = bv;
        float wprev[7];
#pragma unroll
        for (int u = 0; u < 8; u++) {
            float xr[7], wcur[7];
            const float* row = &s[O_HH1 + (2 * rp + 1 + u) * ST1 + tx + 1];
#pragma unroll
            for (int v = 0; v < 7; v++) xr[v] = row[v];
            if (u < 7) {
#pragma unroll
                for (int v = 0; v < 7; v++) wcur[v] = c_w7[u * 7 + v];
#pragma unroll
                for (int v = 0; v < 7; v++) acc0 += xr[v] * wcur[v];
            }
            if (u >= 1) {
#pragma unroll
                for (int v = 0; v < 7; v++) acc1 += xr[v] * wprev[v];
            }
#pragma unroll
            for (int v = 0; v < 7; v++) wprev[v] = wcur[v];
        }
        s[O_CHH1 + (2 * rp) * 32 + tx]     = acc0;
        s[O_CHH1 + (2 * rp + 1) * 32 + tx] = acc1;
    }
    if (tid >= 448) {
        // IDWT level 3 with inline conv3: 64 threads -> REC2 (16x16).
        int t3 = tid - 448;
        int i = t3 >> 3, j = t3 & 7;
        float d = c_b3[0];
#pragma unroll
        for (int u = 0; u < 3; u++)
#pragma unroll
            for (int v = 0; v < 3; v++)
                d += s[O_HH3 + (i + u) * 10 + (j + v)] * c_w3[u * 3 + v];
        float a = s[O_LL3 + (i + 1) * 10 + (j + 1)];
        float b = s[O_LH3 + (i + 1) * 10 + (j + 1)];
        float c = s[O_HL3 + (i + 1) * 10 + (j + 1)];
        *reinterpret_cast<float2*>(&s[O_REC2 + (2 * i) * 16 + 2 * j]) =
            make_float2((a + b + c + d) * 0.5f, (a + b - c - d) * 0.5f);
        *reinterpret_cast<float2*>(&s[O_REC2 + (2 * i + 1) * 16 + 2 * j]) =
            make_float2((a - b + c - d) * 0.5f, (a - b - c + d) * 0.5f);
    }
    __syncthreads();

    // ---- S4: fused IDWT2 + IDWT1 -> global. 256 threads; each owns one lvl2
    //      position -> rec1 2x2 in regs -> 4x4 output pixels (4 x float4). ----
    if (tid < 256) {
        int p = tid >> 4, q = tid & 15;
        float a2 = s[O_REC2 + tid];
        float b2 = s[O_LH2 + (p + 2) * 20 + (q + 2)];
        float c2 = s[O_HL2 + (p + 2) * 20 + (q + 2)];
        float d2 = s[O_CHH2 + tid];
        float r00 = (a2 + b2 + c2 + d2) * 0.5f;
        float r01 = (a2 + b2 - c2 - d2) * 0.5f;
        float r10 = (a2 - b2 + c2 - d2) * 0.5f;
        float r11 = (a2 - b2 - c2 + d2) * 0.5f;

#pragma unroll
        for (int k = 0; k < 2; k++) {
            int i = 2 * p + k;                       // rec1 row
            float ra = k ? r10 : r00;                // rec1(i, 2q)
            float rb = k ? r11 : r01;                // rec1(i, 2q+1)
            float2 b = *reinterpret_cast<const float2*>(&s[O_LH1 + (i + 4) * ST1 + 2 * q + 4]);
            float2 c = *reinterpret_cast<const float2*>(&s[O_HL1 + (i + 4) * ST1 + 2 * q + 4]);
            float2 d = *reinterpret_cast<const float2*>(&s[O_CHH1 + i * 32 + 2 * q]);
            float4 e0, e1;
            e0.x = (ra + b.x + c.x + d.x) * 0.5f;
            e0.y = (ra + b.x - c.x - d.x) * 0.5f;
            e0.z = (rb + b.y + c.y + d.y) * 0.5f;
            e0.w = (rb + b.y - c.y - d.y) * 0.5f;
            e1.x = (ra - b.x + c.x - d.x) * 0.5f;
            e1.y = (ra - b.x - c.x + d.x) * 0.5f;
            e1.z = (rb - b.y + c.y - d.y) * 0.5f;
            e1.w = (rb - b.y - c.y + d.y) * 0.5f;
            int gr = by * T + 2 * i;
            int gc = bx * T + 4 * q;
            *reinterpret_cast<float4*>(out + (size_t)gr * NN + gc)       = e0;
            *reinterpret_cast<float4*>(out + (size_t)(gr + 1) * NN + gc) = e1;
        }
    }
}

extern "C" void kernel_launch(void* const* d_in, const int* in_sizes, int n_in,
                              void* d_out, int out_size)
{
    const float* x = (const float*)d_in[0];
    float* out = (float*)d_out;

    // Runtime weights -> __constant__ (D2D async copies; graph-capturable).
    cudaMemcpyToSymbolAsync(c_w3, d_in[1], 9 * sizeof(float), 0, cudaMemcpyDeviceToDevice);
    cudaMemcpyToSymbolAsync(c_b3, d_in[2], sizeof(float), 0, cudaMemcpyDeviceToDevice);
    cudaMemcpyToSymbolAsync(c_w5, d_in[3], 25 * sizeof(float), 0, cudaMemcpyDeviceToDevice);
    cudaMemcpyToSymbolAsync(c_b5, d_in[4], sizeof(float), 0, cudaMemcpyDeviceToDevice);
    cudaMemcpyToSymbolAsync(c_w7, d_in[5], 49 * sizeof(float), 0, cudaMemcpyDeviceToDevice);
    cudaMemcpyToSymbolAsync(c_b7, d_in[6], sizeof(float), 0, cudaMemcpyDeviceToDevice);

    dim3 grid(NN / T, NN / T);
    fused_wavelet_kernel<<<grid, 512>>>(x, out);
}

// round 6
// speedup vs baseline: 2.1228x; 1.2800x over previous
#include <cuda_runtime.h>

#define T   64
#define NN  4096
#define ST1 42   // lvl1 array row stride (40 rows used, coords [-4,36))

// Shared layout (float offsets).
#define O_LH1  0        // 40x42
#define O_HL1  1680
#define O_HH1  3360
#define O_LL2  5040     // 20x20, coords [-2,18)
#define O_LH2  5440
#define O_HL2  5840
#define O_HH2  6240
#define O_LL3  6640     // 10x10, coords [-1,9)
#define O_LH3  6740
#define O_HL3  6840
#define O_HH3  6940
#define O_CHH2 7040     // 16x16
#define O_CHH1 7296     // 32x32
#define O_REC2 8320     // 16x16
#define SMEM_FLOATS 8576

// Constant weight bank: w7[0..48] w5[49..73] w3[74..82] b7[83] b5[84] b3[85]
__constant__ float c_w[96];
__device__   float g_wstage[96];

#define W7(i) c_w[i]
#define W5(i) c_w[49 + (i)]
#define W3(i) c_w[74 + (i)]
#define B7    c_w[83]
#define B5    c_w[84]
#define B3    c_w[85]

__global__ void pack_weights(const float* __restrict__ w3, const float* __restrict__ b3,
                             const float* __restrict__ w5, const float* __restrict__ b5,
                             const float* __restrict__ w7, const float* __restrict__ b7)
{
    int t = threadIdx.x;
    float v = 0.f;
    if (t < 49)       v = w7[t];
    else if (t < 74)  v = w5[t - 49];
    else if (t < 83)  v = w3[t - 74];
    else if (t == 83) v = b7[0];
    else if (t == 84) v = b5[0];
    else if (t == 85) v = b3[0];
    if (t < 96) g_wstage[t] = v;
}

__global__ __launch_bounds__(512) void fused_wavelet_kernel(
    const float* __restrict__ x, float* __restrict__ out)
{
    __shared__ float s[SMEM_FLOATS];
    const int tid = threadIdx.x;
    const int bx = blockIdx.x, by = blockIdx.y;

    // ---- S1: fused level-1 + level-2 DWT. 400 threads; each owns one lvl2
    //      position = 2x2 lvl1 quads = 4x4 input pixels (4 x float4 from gmem).
    if (tid < 400) {
        int ap = tid / 20, aq = tid - ap * 20;
        int gr = by * T - 8 + 4 * ap;     // 4-aligned group; all-in or all-out
        int gc = bx * T - 8 + 4 * aq;
        float4 A = make_float4(0.f, 0.f, 0.f, 0.f), B = A, C = A, D = A;
        if ((unsigned)gr < NN && (unsigned)gc < NN) {
            const float* p = x + (size_t)gr * NN + gc;
            A = *reinterpret_cast<const float4*>(p);
            B = *reinterpret_cast<const float4*>(p + NN);
            C = *reinterpret_cast<const float4*>(p + 2 * NN);
            D = *reinterpret_cast<const float4*>(p + 3 * NN);
        }
        float ll00 = (A.x + A.y + B.x + B.y) * 0.5f;
        float lh00 = (A.x + A.y - B.x - B.y) * 0.5f;
        float hl00 = (A.x - A.y + B.x - B.y) * 0.5f;
        float hh00 = (A.x - A.y - B.x + B.y) * 0.5f;
        float ll01 = (A.z + A.w + B.z + B.w) * 0.5f;
        float lh01 = (A.z + A.w - B.z - B.w) * 0.5f;
        float hl01 = (A.z - A.w + B.z - B.w) * 0.5f;
        float hh01 = (A.z - A.w - B.z + B.w) * 0.5f;
        float ll10 = (C.x + C.y + D.x + D.y) * 0.5f;
        float lh10 = (C.x + C.y - D.x - D.y) * 0.5f;
        float hl10 = (C.x - C.y + D.x - D.y) * 0.5f;
        float hh10 = (C.x - C.y - D.x + D.y) * 0.5f;
        float ll11 = (C.z + C.w + D.z + D.w) * 0.5f;
        float lh11 = (C.z + C.w - D.z - D.w) * 0.5f;
        float hl11 = (C.z - C.w + D.z - D.w) * 0.5f;
        float hh11 = (C.z - C.w - D.z + D.w) * 0.5f;

        int r0 = (2 * ap) * ST1 + 2 * aq;
        int r1 = r0 + ST1;
        *reinterpret_cast<float2*>(&s[O_LH1 + r0]) = make_float2(lh00, lh01);
        *reinterpret_cast<float2*>(&s[O_LH1 + r1]) = make_float2(lh10, lh11);
        *reinterpret_cast<float2*>(&s[O_HL1 + r0]) = make_float2(hl00, hl01);
        *reinterpret_cast<float2*>(&s[O_HL1 + r1]) = make_float2(hl10, hl11);
        *reinterpret_cast<float2*>(&s[O_HH1 + r0]) = make_float2(hh00, hh01);
        *reinterpret_cast<float2*>(&s[O_HH1 + r1]) = make_float2(hh10, hh11);

        s[O_LL2 + tid] = (ll00 + ll01 + ll10 + ll11) * 0.5f;
        s[O_LH2 + tid] = (ll00 + ll01 - ll10 - ll11) * 0.5f;
        s[O_HL2 + tid] = (ll00 - ll01 + ll10 - ll11) * 0.5f;
        s[O_HH2 + tid] = (ll00 - ll01 - ll10 + ll11) * 0.5f;
    }
    __syncthreads();

    // ---- S2 (one phase, disjoint ranges):
    //      tid 0-255:   conv7 on HH1 -> CHH1, 4 rows/thread
    //      tid 256-383: conv5 on HH2 -> CHH2, 2 rows/thread
    //      tid 384-483: level-3 DWT
    if (tid < 256) {
        int rg = (tid >> 5) * 4;     // output rows rg..rg+3
        int tx = tid & 31;
        float bv = B7;
        float acc0 = bv, acc1 = bv, acc2 = bv, acc3 = bv;
#pragma unroll
        for (int u = 0; u < 10; u++) {
            float xr[7];
            const float* row = &s[O_HH1 + (rg + 1 + u) * ST1 + tx + 1];
#pragma unroll
            for (int v = 0; v < 7; v++) xr[v] = row[v];
#pragma unroll
            for (int v = 0; v < 7; v++) {
                if (u - 0 >= 0 && u - 0 < 7) acc0 += xr[v] * W7((u - 0) * 7 + v);
                if (u - 1 >= 0 && u - 1 < 7) acc1 += xr[v] * W7((u - 1) * 7 + v);
                if (u - 2 >= 0 && u - 2 < 7) acc2 += xr[v] * W7((u - 2) * 7 + v);
                if (u - 3 >= 0 && u - 3 < 7) acc3 += xr[v] * W7((u - 3) * 7 + v);
            }
        }
        s[O_CHH1 + (rg + 0) * 32 + tx] = acc0;
        s[O_CHH1 + (rg + 1) * 32 + tx] = acc1;
        s[O_CHH1 + (rg + 2) * 32 + tx] = acc2;
        s[O_CHH1 + (rg + 3) * 32 + tx] = acc3;
    } else if (tid < 384) {
        int t2 = tid - 256;
        int rp = t2 >> 4, q = t2 & 15;   // output rows 2rp, 2rp+1, col q
        float bv = B5;
        float acc0 = bv, acc1 = bv;
#pragma unroll
        for (int u = 0; u < 6; u++) {
            float xr[5];
            const float* row = &s[O_HH2 + (2 * rp + u) * 20 + q];
#pragma unroll
            for (int v = 0; v < 5; v++) xr[v] = row[v];
#pragma unroll
            for (int v = 0; v < 5; v++) {
                if (u < 5)  acc0 += xr[v] * W5(u * 5 + v);
                if (u >= 1) acc1 += xr[v] * W5((u - 1) * 5 + v);
            }
        }
        s[O_CHH2 + (2 * rp) * 16 + q]     = acc0;
        s[O_CHH2 + (2 * rp + 1) * 16 + q] = acc1;
    } else if (tid < 484) {
        int t3 = tid - 384;
        int as = t3 / 10, at = t3 - as * 10;
        float2 t0 = *reinterpret_cast<const float2*>(&s[O_LL2 + (2 * as) * 20 + 2 * at]);
        float2 t1 = *reinterpret_cast<const float2*>(&s[O_LL2 + (2 * as + 1) * 20 + 2 * at]);
        s[O_LL3 + t3] = (t0.x + t0.y + t1.x + t1.y) * 0.5f;
        s[O_LH3 + t3] = (t0.x + t0.y - t1.x - t1.y) * 0.5f;
        s[O_HL3 + t3] = (t0.x - t0.y + t1.x - t1.y) * 0.5f;
        s[O_HH3 + t3] = (t0.x - t0.y - t1.x + t1.y) * 0.5f;
    }
    __syncthreads();

    // ---- S3: IDWT level 3 with inline conv3 (64 threads) -> REC2 (16x16) ----
    if (tid < 64) {
        int i = tid >> 3, j = tid & 7;
        float d = B3;
#pragma unroll
        for (int u = 0; u < 3; u++)
#pragma unroll
            for (int v = 0; v < 3; v++)
                d += s[O_HH3 + (i + u) * 10 + (j + v)] * W3(u * 3 + v);
        float a = s[O_LL3 + (i + 1) * 10 + (j + 1)];
        float b = s[O_LH3 + (i + 1) * 10 + (j + 1)];
        float c = s[O_HL3 + (i + 1) * 10 + (j + 1)];
        *reinterpret_cast<float2*>(&s[O_REC2 + (2 * i) * 16 + 2 * j]) =
            make_float2((a + b + c + d) * 0.5f, (a + b - c - d) * 0.5f);
        *reinterpret_cast<float2*>(&s[O_REC2 + (2 * i + 1) * 16 + 2 * j]) =
            make_float2((a - b + c - d) * 0.5f, (a - b - c + d) * 0.5f);
    }
    __syncthreads();

    // ---- S4: fused IDWT2 + IDWT1 -> global. 256 threads; each owns one lvl2
    //      position -> rec1 2x2 in regs -> 4x4 output pixels (4 x float4). ----
    if (tid < 256) {
        int p = tid >> 4, q = tid & 15;
        float a2 = s[O_REC2 + tid];
        float b2 = s[O_LH2 + (p + 2) * 20 + (q + 2)];
        float c2 = s[O_HL2 + (p + 2) * 20 + (q + 2)];
        float d2 = s[O_CHH2 + tid];
        float r00 = (a2 + b2 + c2 + d2) * 0.5f;
        float r01 = (a2 + b2 - c2 - d2) * 0.5f;
        float r10 = (a2 - b2 + c2 - d2) * 0.5f;
        float r11 = (a2 - b2 - c2 + d2) * 0.5f;

#pragma unroll
        for (int k = 0; k < 2; k++) {
            int i = 2 * p + k;
            float ra = k ? r10 : r00;
            float rb = k ? r11 : r01;
            float2 b = *reinterpret_cast<const float2*>(&s[O_LH1 + (i + 4) * ST1 + 2 * q + 4]);
            float2 c = *reinterpret_cast<const float2*>(&s[O_HL1 + (i + 4) * ST1 + 2 * q + 4]);
            float2 d = *reinterpret_cast<const float2*>(&s[O_CHH1 + i * 32 + 2 * q]);
            float4 e0, e1;
            e0.x = (ra + b.x + c.x + d.x) * 0.5f;
            e0.y = (ra + b.x - c.x - d.x) * 0.5f;
            e0.z = (rb + b.y + c.y + d.y) * 0.5f;
            e0.w = (rb + b.y - c.y - d.y) * 0.5f;
            e1.x = (ra - b.x + c.x - d.x) * 0.5f;
            e1.y = (ra - b.x - c.x + d.x) * 0.5f;
            e1.z = (rb - b.y + c.y - d.y) * 0.5f;
            e1.w = (rb - b.y - c.y + d.y) * 0.5f;
            int gr = by * T + 2 * i;
            int gc = bx * T + 4 * q;
            *reinterpret_cast<float4*>(out + (size_t)gr * NN + gc)       = e0;
            *reinterpret_cast<float4*>(out + (size_t)(gr + 1) * NN + gc) = e1;
        }
    }
}

extern "C" void kernel_launch(void* const* d_in, const int* in_sizes, int n_in,
                              void* d_out, int out_size)
{
    const float* x = (const float*)d_in[0];
    float* out = (float*)d_out;

    // Gather all weights into one staging buffer (1 kernel), then ONE
    // memcpy node into constant memory. 3 graph nodes total.
    pack_weights<<<1, 96>>>((const float*)d_in[1], (const float*)d_in[2],
                            (const float*)d_in[3], (const float*)d_in[4],
                            (const float*)d_in[5], (const float*)d_in[6]);
    void* stage_ptr = nullptr;
    cudaGetSymbolAddress(&stage_ptr, g_wstage);
    cudaMemcpyToSymbolAsync(c_w, stage_ptr, 96 * sizeof(float), 0,
                            cudaMemcpyDeviceToDevice);

    dim3 grid(NN / T, NN / T);
    fused_wavelet_kernel<<<grid, 512>>>(x, out);
}

// round 7
// speedup vs baseline: 2.1369x; 1.0066x over previous
#include <cuda_runtime.h>

#define T   64
#define NN  4096
#define ST1 42   // lvl1 array row stride (40 rows used)

// Shared layout (float offsets).
// LH1/HL1: stored col = logical+4 (cols 0..39). HH1: stored col = logical+5
// (cols 1..40) so conv7 2-col windows start even. Rows: stored = logical+4.
#define O_LH1  0        // 40x42
#define O_HL1  1680
#define O_HH1  3360
#define O_LL2  5040     // 20x20, coords [-2,18), stored = logical+2
#define O_LH2  5440
#define O_HL2  5840
#define O_HH2  6240
#define O_LL3  6640     // 10x10, coords [-1,9)
#define O_LH3  6740
#define O_HL3  6840
#define O_HH3  6940
#define O_CHH2 7040     // 16x16
#define O_CHH1 7296     // 32x32
#define O_REC2 8320     // 16x16
#define SMEM_FLOATS 8576

// Constant weight bank: w7[0..48] w5[49..73] w3[74..82] b7[83] b5[84] b3[85]
__constant__ float c_w[96];
__device__   float g_wstage[96];

#define W7(i) c_w[i]
#define W5(i) c_w[49 + (i)]
#define W3(i) c_w[74 + (i)]
#define B7    c_w[83]
#define B5    c_w[84]
#define B3    c_w[85]

__global__ void pack_weights(const float* __restrict__ w3, const float* __restrict__ b3,
                             const float* __restrict__ w5, const float* __restrict__ b5,
                             const float* __restrict__ w7, const float* __restrict__ b7)
{
    int t = threadIdx.x;
    float v = 0.f;
    if (t < 49)       v = w7[t];
    else if (t < 74)  v = w5[t - 49];
    else if (t < 83)  v = w3[t - 74];
    else if (t == 83) v = b7[0];
    else if (t == 84) v = b5[0];
    else if (t == 85) v = b3[0];
    if (t < 96) g_wstage[t] = v;
}

__global__ __launch_bounds__(512, 3) void fused_wavelet_kernel(
    const float* __restrict__ x, float* __restrict__ out)
{
    __shared__ float s[SMEM_FLOATS];
    const int tid = threadIdx.x;
    const int bx = blockIdx.x, by = blockIdx.y;

    // ---- S1: fused level-1 + level-2 DWT. 400 threads; each owns one lvl2
    //      position = 2x2 lvl1 quads = 4x4 input pixels (4 x float4 from gmem).
    if (tid < 400) {
        int ap = tid / 20, aq = tid - ap * 20;
        int gr = by * T - 8 + 4 * ap;
        int gc = bx * T - 8 + 4 * aq;
        float4 A = make_float4(0.f, 0.f, 0.f, 0.f), B = A, C = A, D = A;
        if ((unsigned)gr < NN && (unsigned)gc < NN) {
            const float* p = x + (size_t)gr * NN + gc;
            A = *reinterpret_cast<const float4*>(p);
            B = *reinterpret_cast<const float4*>(p + NN);
            C = *reinterpret_cast<const float4*>(p + 2 * NN);
            D = *reinterpret_cast<const float4*>(p + 3 * NN);
        }
        float ll00 = (A.x + A.y + B.x + B.y) * 0.5f;
        float lh00 = (A.x + A.y - B.x - B.y) * 0.5f;
        float hl00 = (A.x - A.y + B.x - B.y) * 0.5f;
        float hh00 = (A.x - A.y - B.x + B.y) * 0.5f;
        float ll01 = (A.z + A.w + B.z + B.w) * 0.5f;
        float lh01 = (A.z + A.w - B.z - B.w) * 0.5f;
        float hl01 = (A.z - A.w + B.z - B.w) * 0.5f;
        float hh01 = (A.z - A.w - B.z + B.w) * 0.5f;
        float ll10 = (C.x + C.y + D.x + D.y) * 0.5f;
        float lh10 = (C.x + C.y - D.x - D.y) * 0.5f;
        float hl10 = (C.x - C.y + D.x - D.y) * 0.5f;
        float hh10 = (C.x - C.y - D.x + D.y) * 0.5f;
        float ll11 = (C.z + C.w + D.z + D.w) * 0.5f;
        float lh11 = (C.z + C.w - D.z - D.w) * 0.5f;
        float hl11 = (C.z - C.w + D.z - D.w) * 0.5f;
        float hh11 = (C.z - C.w - D.z + D.w) * 0.5f;

        int r0 = (2 * ap) * ST1 + 2 * aq;
        int r1 = r0 + ST1;
        *reinterpret_cast<float2*>(&s[O_LH1 + r0]) = make_float2(lh00, lh01);
        *reinterpret_cast<float2*>(&s[O_LH1 + r1]) = make_float2(lh10, lh11);
        *reinterpret_cast<float2*>(&s[O_HL1 + r0]) = make_float2(hl00, hl01);
        *reinterpret_cast<float2*>(&s[O_HL1 + r1]) = make_float2(hl10, hl11);
        // HH1 shifted by +1 column (scalar stores).
        s[O_HH1 + r0 + 1] = hh00;
        s[O_HH1 + r0 + 2] = hh01;
        s[O_HH1 + r1 + 1] = hh10;
        s[O_HH1 + r1 + 2] = hh11;

        s[O_LL2 + tid] = (ll00 + ll01 + ll10 + ll11) * 0.5f;
        s[O_LH2 + tid] = (ll00 + ll01 - ll10 - ll11) * 0.5f;
        s[O_HL2 + tid] = (ll00 - ll01 + ll10 - ll11) * 0.5f;
        s[O_HH2 + tid] = (ll00 - ll01 - ll10 + ll11) * 0.5f;
    }
    __syncthreads();

    // ---- S2 (one phase, disjoint ranges):
    //   tid 0-127:   conv7 on HH1 -> CHH1. 2 cols x 4 rows per thread.
    //   tid 128-191: conv5 on HH2 -> CHH2. 2 cols x 2 rows per thread.
    //   tid 192-291: level-3 DWT.
    if (tid < 128) {
        int r = tid >> 4;          // 0..7 -> output rows 4r..4r+3
        int c = tid & 15;          // col pair: output cols 2c, 2c+1
        float bv = B7;
        float acc[4][2];
#pragma unroll
        for (int k = 0; k < 4; k++) { acc[k][0] = bv; acc[k][1] = bv; }
#pragma unroll
        for (int u = 0; u < 10; u++) {
            // window cols stored 2c+2 .. 2c+9 (8 floats, float2-aligned)
            const float* row = &s[O_HH1 + (4 * r + 1 + u) * ST1 + 2 * c + 2];
            float xr[8];
            *reinterpret_cast<float2*>(&xr[0]) = *reinterpret_cast<const float2*>(row);
            *reinterpret_cast<float2*>(&xr[2]) = *reinterpret_cast<const float2*>(row + 2);
            *reinterpret_cast<float2*>(&xr[4]) = *reinterpret_cast<const float2*>(row + 4);
            *reinterpret_cast<float2*>(&xr[6]) = *reinterpret_cast<const float2*>(row + 6);
#pragma unroll
            for (int k = 0; k < 4; k++) {
                int uu = u - k;
                if (uu >= 0 && uu < 7) {
#pragma unroll
                    for (int v = 0; v < 7; v++) {
                        float w = W7(uu * 7 + v);
                        acc[k][0] += xr[v] * w;
                        acc[k][1] += xr[v + 1] * w;
                    }
                }
            }
        }
#pragma unroll
        for (int k = 0; k < 4; k++)
            *reinterpret_cast<float2*>(&s[O_CHH1 + (4 * r + k) * 32 + 2 * c]) =
                make_float2(acc[k][0], acc[k][1]);
    } else if (tid < 192) {
        int t2 = tid - 128;
        int r = t2 >> 3;           // 0..7 -> output rows 2r, 2r+1
        int c = t2 & 7;            // col pair: output cols 2c, 2c+1
        float bv = B5;
        float acc[2][2];
        acc[0][0] = acc[0][1] = acc[1][0] = acc[1][1] = bv;
#pragma unroll
        for (int u = 0; u < 6; u++) {
            // window cols stored 2c .. 2c+5 (6 floats, float2-aligned)
            const float* row = &s[O_HH2 + (2 * r + u) * 20 + 2 * c];
            float xr[6];
            *reinterpret_cast<float2*>(&xr[0]) = *reinterpret_cast<const float2*>(row);
            *reinterpret_cast<float2*>(&xr[2]) = *reinterpret_cast<const float2*>(row + 2);
            *reinterpret_cast<float2*>(&xr[4]) = *reinterpret_cast<const float2*>(row + 4);
#pragma unroll
            for (int k = 0; k < 2; k++) {
                int uu = u - k;
                if (uu >= 0 && uu < 5) {
#pragma unroll
                    for (int v = 0; v < 5; v++) {
                        float w = W5(uu * 5 + v);
                        acc[k][0] += xr[v] * w;
                        acc[k][1] += xr[v + 1] * w;
                    }
                }
            }
        }
        *reinterpret_cast<float2*>(&s[O_CHH2 + (2 * r) * 16 + 2 * c]) =
            make_float2(acc[0][0], acc[0][1]);
        *reinterpret_cast<float2*>(&s[O_CHH2 + (2 * r + 1) * 16 + 2 * c]) =
            make_float2(acc[1][0], acc[1][1]);
    } else if (tid < 292) {
        int t3 = tid - 192;
        int as = t3 / 10, at = t3 - as * 10;
        float2 t0 = *reinterpret_cast<const float2*>(&s[O_LL2 + (2 * as) * 20 + 2 * at]);
        float2 t1 = *reinterpret_cast<const float2*>(&s[O_LL2 + (2 * as + 1) * 20 + 2 * at]);
        s[O_LL3 + t3] = (t0.x + t0.y + t1.x + t1.y) * 0.5f;
        s[O_LH3 + t3] = (t0.x + t0.y - t1.x - t1.y) * 0.5f;
        s[O_HL3 + t3] = (t0.x - t0.y + t1.x - t1.y) * 0.5f;
        s[O_HH3 + t3] = (t0.x - t0.y - t1.x + t1.y) * 0.5f;
    }
    __syncthreads();

    // ---- S3: IDWT level 3 with inline conv3 (64 threads) -> REC2 (16x16) ----
    if (tid < 64) {
        int i = tid >> 3, j = tid & 7;
        float d = B3;
#pragma unroll
        for (int u = 0; u < 3; u++)
#pragma unroll
            for (int v = 0; v < 3; v++)
                d += s[O_HH3 + (i + u) * 10 + (j + v)] * W3(u * 3 + v);
        float a = s[O_LL3 + (i + 1) * 10 + (j + 1)];
        float b = s[O_LH3 + (i + 1) * 10 + (j + 1)];
        float c = s[O_HL3 + (i + 1) * 10 + (j + 1)];
        *reinterpret_cast<float2*>(&s[O_REC2 + (2 * i) * 16 + 2 * j]) =
            make_float2((a + b + c + d) * 0.5f, (a + b - c - d) * 0.5f);
        *reinterpret_cast<float2*>(&s[O_REC2 + (2 * i + 1) * 16 + 2 * j]) =
            make_float2((a - b + c - d) * 0.5f, (a - b - c + d) * 0.5f);
    }
    __syncthreads();

    // ---- S4: fused IDWT2 + IDWT1 -> global. 256 threads. ----
    if (tid < 256) {
        int p = tid >> 4, q = tid & 15;
        float a2 = s[O_REC2 + tid];
        float b2 = s[O_LH2 + (p + 2) * 20 + (q + 2)];
        float c2 = s[O_HL2 + (p + 2) * 20 + (q + 2)];
        float d2 = s[O_CHH2 + tid];
        float r00 = (a2 + b2 + c2 + d2) * 0.5f;
        float r01 = (a2 + b2 - c2 - d2) * 0.5f;
        float r10 = (a2 - b2 + c2 - d2) * 0.5f;
        float r11 = (a2 - b2 - c2 + d2) * 0.5f;

#pragma unroll
        for (int k = 0; k < 2; k++) {
            int i = 2 * p + k;
            float ra = k ? r10 : r00;
            float rb = k ? r11 : r01;
            float2 b = *reinterpret_cast<const float2*>(&s[O_LH1 + (i + 4) * ST1 + 2 * q + 4]);
            float2 c = *reinterpret_cast<const float2*>(&s[O_HL1 + (i + 4) * ST1 + 2 * q + 4]);
            float2 d = *reinterpret_cast<const float2*>(&s[O_CHH1 + i * 32 + 2 * q]);
            float4 e0, e1;
            e0.x = (ra + b.x + c.x + d.x) * 0.5f;
            e0.y = (ra + b.x - c.x - d.x) * 0.5f;
            e0.z = (rb + b.y + c.y + d.y) * 0.5f;
            e0.w = (rb + b.y - c.y - d.y) * 0.5f;
            e1.x = (ra - b.x + c.x - d.x) * 0.5f;
            e1.y = (ra - b.x - c.x + d.x) * 0.5f;
            e1.z = (rb - b.y + c.y - d.y) * 0.5f;
            e1.w = (rb - b.y - c.y + d.y) * 0.5f;
            int gr = by * T + 2 * i;
            int gc = bx * T + 4 * q;
            *reinterpret_cast<float4*>(out + (size_t)gr * NN + gc)       = e0;
            *reinterpret_cast<float4*>(out + (size_t)(gr + 1) * NN + gc) = e1;
        }
    }
}

extern "C" void kernel_launch(void* const* d_in, const int* in_sizes, int n_in,
                              void* d_out, int out_size)
{
    const float* x = (const float*)d_in[0];
    float* out = (float*)d_out;

    pack_weights<<<1, 96>>>((const float*)d_in[1], (const float*)d_in[2],
                            (const float*)d_in[3], (const float*)d_in[4],
                            (const float*)d_in[5], (const float*)d_in[6]);
    void* stage_ptr = nullptr;
    cudaGetSymbolAddress(&stage_ptr, g_wstage);
    cudaMemcpyToSymbolAsync(c_w, stage_ptr, 96 * sizeof(float), 0,
                            cudaMemcpyDeviceToDevice);

    dim3 grid(NN / T, NN / T);
    fused_wavelet_kernel<<<grid, 512>>>(x, out);
}

// round 8
// speedup vs baseline: 2.1655x; 1.0134x over previous
#include <cuda_runtime.h>

#define TR  128       // tile rows (output)
#define TC  64        // tile cols (output)
#define NN  4096
#define ST1 42        // lvl1 array col stride

// Shared layout (float offsets), dynamic smem.
// lvl1 arrays: 72 rows x ST1. stored row = logical+4.
// LH1/HL1 stored col = logical+4; HH1 stored col = logical+5.
#define O_LH1  0        // 72x42 = 3024
#define O_HL1  3024
#define O_HH1  6048
#define O_LL2  9072     // 36x20, stored = logical+2
#define O_LH2  9792
#define O_HL2  10512
#define O_HH2  11232
#define O_LL3  11952    // 18x10, stored = logical+1
#define O_LH3  12132
#define O_HL3  12312
#define O_HH3  12492
#define O_CHH2 12672    // 32x16
#define O_CHH1 13184    // 64x32
#define O_REC2 15232    // 32x16
#define SMEM_FLOATS 15744
#define SMEM_BYTES (SMEM_FLOATS * 4)

// Constant weight bank: w7[0..48] w5[49..73] w3[74..82] b7[83] b5[84] b3[85]
__constant__ float c_w[96];
__device__   float g_wstage[96];

#define W7(i) c_w[i]
#define W5(i) c_w[49 + (i)]
#define W3(i) c_w[74 + (i)]
#define B7    c_w[83]
#define B5    c_w[84]
#define B3    c_w[85]

__global__ void pack_weights(const float* __restrict__ w3, const float* __restrict__ b3,
                             const float* __restrict__ w5, const float* __restrict__ b5,
                             const float* __restrict__ w7, const float* __restrict__ b7)
{
    int t = threadIdx.x;
    float v = 0.f;
    if (t < 49)       v = w7[t];
    else if (t < 74)  v = w5[t - 49];
    else if (t < 83)  v = w3[t - 74];
    else if (t == 83) v = b7[0];
    else if (t == 84) v = b5[0];
    else if (t == 85) v = b3[0];
    if (t < 96) g_wstage[t] = v;
}

__global__ __launch_bounds__(512, 3) void fused_wavelet_kernel(
    const float* __restrict__ x, float* __restrict__ out)
{
    extern __shared__ float s[];
    const int tid = threadIdx.x;
    const int bx = blockIdx.x, by = blockIdx.y;

    // ---- S1: fused level-1 + level-2 DWT. 720 lvl2 positions (36x20);
    //      each covers 2x2 lvl1 quads = 4x4 input pixels (4 x float4).
    for (int idx = tid; idx < 720; idx += 512) {
        int ap = idx / 20, aq = idx - ap * 20;
        int gr = by * TR - 8 + 4 * ap;
        int gc = bx * TC - 8 + 4 * aq;
        float4 A = make_float4(0.f, 0.f, 0.f, 0.f), B = A, C = A, D = A;
        if ((unsigned)gr < NN && (unsigned)gc < NN) {
            const float* p = x + (size_t)gr * NN + gc;
            A = *reinterpret_cast<const float4*>(p);
            B = *reinterpret_cast<const float4*>(p + NN);
            C = *reinterpret_cast<const float4*>(p + 2 * NN);
            D = *reinterpret_cast<const float4*>(p + 3 * NN);
        }
        float ll00 = (A.x + A.y + B.x + B.y) * 0.5f;
        float lh00 = (A.x + A.y - B.x - B.y) * 0.5f;
        float hl00 = (A.x - A.y + B.x - B.y) * 0.5f;
        float hh00 = (A.x - A.y - B.x + B.y) * 0.5f;
        float ll01 = (A.z + A.w + B.z + B.w) * 0.5f;
        float lh01 = (A.z + A.w - B.z - B.w) * 0.5f;
        float hl01 = (A.z - A.w + B.z - B.w) * 0.5f;
        float hh01 = (A.z - A.w - B.z + B.w) * 0.5f;
        float ll10 = (C.x + C.y + D.x + D.y) * 0.5f;
        float lh10 = (C.x + C.y - D.x - D.y) * 0.5f;
        float hl10 = (C.x - C.y + D.x - D.y) * 0.5f;
        float hh10 = (C.x - C.y - D.x + D.y) * 0.5f;
        float ll11 = (C.z + C.w + D.z + D.w) * 0.5f;
        float lh11 = (C.z + C.w - D.z - D.w) * 0.5f;
        float hl11 = (C.z - C.w + D.z - D.w) * 0.5f;
        float hh11 = (C.z - C.w - D.z + D.w) * 0.5f;

        int r0 = (2 * ap) * ST1 + 2 * aq;
        int r1 = r0 + ST1;
        *reinterpret_cast<float2*>(&s[O_LH1 + r0]) = make_float2(lh00, lh01);
        *reinterpret_cast<float2*>(&s[O_LH1 + r1]) = make_float2(lh10, lh11);
        *reinterpret_cast<float2*>(&s[O_HL1 + r0]) = make_float2(hl00, hl01);
        *reinterpret_cast<float2*>(&s[O_HL1 + r1]) = make_float2(hl10, hl11);
        s[O_HH1 + r0 + 1] = hh00;
        s[O_HH1 + r0 + 2] = hh01;
        s[O_HH1 + r1 + 1] = hh10;
        s[O_HH1 + r1 + 2] = hh11;

        s[O_LL2 + idx] = (ll00 + ll01 + ll10 + ll11) * 0.5f;
        s[O_LH2 + idx] = (ll00 + ll01 - ll10 - ll11) * 0.5f;
        s[O_HL2 + idx] = (ll00 - ll01 + ll10 - ll11) * 0.5f;
        s[O_HH2 + idx] = (ll00 - ll01 - ll10 + ll11) * 0.5f;
    }
    __syncthreads();

    // ---- S2 (one phase, disjoint ranges):
    //   tid 0-255:   conv7 on HH1 -> CHH1 (64x32). 2 cols x 4 rows per thread.
    //   tid 256-383: conv5 on HH2 -> CHH2 (32x16). 2x2 per thread.
    //   tid 384-511: level-3 DWT (180 positions, strided).
    if (tid < 256) {
        int r = tid >> 4;          // 0..15 -> output rows 4r..4r+3
        int c = tid & 15;          // output cols 2c, 2c+1
        float bv = B7;
        float acc[4][2];
#pragma unroll
        for (int k = 0; k < 4; k++) { acc[k][0] = bv; acc[k][1] = bv; }
#pragma unroll
        for (int u = 0; u < 10; u++) {
            const float* row = &s[O_HH1 + (4 * r + 1 + u) * ST1 + 2 * c + 2];
            float xr[8];
            *reinterpret_cast<float2*>(&xr[0]) = *reinterpret_cast<const float2*>(row);
            *reinterpret_cast<float2*>(&xr[2]) = *reinterpret_cast<const float2*>(row + 2);
            *reinterpret_cast<float2*>(&xr[4]) = *reinterpret_cast<const float2*>(row + 4);
            *reinterpret_cast<float2*>(&xr[6]) = *reinterpret_cast<const float2*>(row + 6);
#pragma unroll
            for (int k = 0; k < 4; k++) {
                int uu = u - k;
                if (uu >= 0 && uu < 7) {
#pragma unroll
                    for (int v = 0; v < 7; v++) {
                        float w = W7(uu * 7 + v);
                        acc[k][0] += xr[v] * w;
                        acc[k][1] += xr[v + 1] * w;
                    }
                }
            }
        }
#pragma unroll
        for (int k = 0; k < 4; k++)
            *reinterpret_cast<float2*>(&s[O_CHH1 + (4 * r + k) * 32 + 2 * c]) =
                make_float2(acc[k][0], acc[k][1]);
    } else if (tid < 384) {
        int t2 = tid - 256;
        int r = t2 >> 3;           // 0..15 -> output rows 2r, 2r+1
        int c = t2 & 7;            // output cols 2c, 2c+1
        float bv = B5;
        float acc[2][2];
        acc[0][0] = acc[0][1] = acc[1][0] = acc[1][1] = bv;
#pragma unroll
        for (int u = 0; u < 6; u++) {
            const float* row = &s[O_HH2 + (2 * r + u) * 20 + 2 * c];
            float xr[6];
            *reinterpret_cast<float2*>(&xr[0]) = *reinterpret_cast<const float2*>(row);
            *reinterpret_cast<float2*>(&xr[2]) = *reinterpret_cast<const float2*>(row + 2);
            *reinterpret_cast<float2*>(&xr[4]) = *reinterpret_cast<const float2*>(row + 4);
#pragma unroll
            for (int k = 0; k < 2; k++) {
                int uu = u - k;
                if (uu >= 0 && uu < 5) {
#pragma unroll
                    for (int v = 0; v < 5; v++) {
                        float w = W5(uu * 5 + v);
                        acc[k][0] += xr[v] * w;
                        acc[k][1] += xr[v + 1] * w;
                    }
                }
            }
        }
        *reinterpret_cast<float2*>(&s[O_CHH2 + (2 * r) * 16 + 2 * c]) =
            make_float2(acc[0][0], acc[0][1]);
        *reinterpret_cast<float2*>(&s[O_CHH2 + (2 * r + 1) * 16 + 2 * c]) =
            make_float2(acc[1][0], acc[1][1]);
    } else {
        for (int t3 = tid - 384; t3 < 180; t3 += 128) {
            int as = t3 / 10, at = t3 - as * 10;
            float2 t0 = *reinterpret_cast<const float2*>(&s[O_LL2 + (2 * as) * 20 + 2 * at]);
            float2 t1 = *reinterpret_cast<const float2*>(&s[O_LL2 + (2 * as + 1) * 20 + 2 * at]);
            s[O_LL3 + t3] = (t0.x + t0.y + t1.x + t1.y) * 0.5f;
            s[O_LH3 + t3] = (t0.x + t0.y - t1.x - t1.y) * 0.5f;
            s[O_HL3 + t3] = (t0.x - t0.y + t1.x - t1.y) * 0.5f;
            s[O_HH3 + t3] = (t0.x - t0.y - t1.x + t1.y) * 0.5f;
        }
    }
    __syncthreads();

    // ---- S3: IDWT level 3 with inline conv3 (128 threads) -> REC2 (32x16) ----
    if (tid < 128) {
        int i = tid >> 3, j = tid & 7;     // lvl3 logical position (16x8)
        float d = B3;
#pragma unroll
        for (int u = 0; u < 3; u++)
#pragma unroll
            for (int v = 0; v < 3; v++)
                d += s[O_HH3 + (i + u) * 10 + (j + v)] * W3(u * 3 + v);
        float a = s[O_LL3 + (i + 1) * 10 + (j + 1)];
        float b = s[O_LH3 + (i + 1) * 10 + (j + 1)];
        float c = s[O_HL3 + (i + 1) * 10 + (j + 1)];
        *reinterpret_cast<float2*>(&s[O_REC2 + (2 * i) * 16 + 2 * j]) =
            make_float2((a + b + c + d) * 0.5f, (a + b - c - d) * 0.5f);
        *reinterpret_cast<float2*>(&s[O_REC2 + (2 * i + 1) * 16 + 2 * j]) =
            make_float2((a - b + c - d) * 0.5f, (a - b - c + d) * 0.5f);
    }
    __syncthreads();

    // ---- S4: fused IDWT2 + IDWT1 -> global. 512 threads; each owns one lvl2
    //      position (32x16) -> rec1 2x2 in regs -> 4x4 output pixels. ----
    {
        int p = tid >> 4, q = tid & 15;
        float a2 = s[O_REC2 + tid];
        float b2 = s[O_LH2 + (p + 2) * 20 + (q + 2)];
        float c2 = s[O_HL2 + (p + 2) * 20 + (q + 2)];
        float d2 = s[O_CHH2 + tid];
        float r00 = (a2 + b2 + c2 + d2) * 0.5f;
        float r01 = (a2 + b2 - c2 - d2) * 0.5f;
        float r10 = (a2 - b2 + c2 - d2) * 0.5f;
        float r11 = (a2 - b2 - c2 + d2) * 0.5f;

#pragma unroll
        for (int k = 0; k < 2; k++) {
            int i = 2 * p + k;             // rec1 / lvl1 logical row (0..63)
            float ra = k ? r10 : r00;
            float rb = k ? r11 : r01;
            float2 b = *reinterpret_cast<const float2*>(&s[O_LH1 + (i + 4) * ST1 + 2 * q + 4]);
            float2 c = *reinterpret_cast<const float2*>(&s[O_HL1 + (i + 4) * ST1 + 2 * q + 4]);
            float2 d = *reinterpret_cast<const float2*>(&s[O_CHH1 + i * 32 + 2 * q]);
            float4 e0, e1;
            e0.x = (ra + b.x + c.x + d.x) * 0.5f;
            e0.y = (ra + b.x - c.x - d.x) * 0.5f;
            e0.z = (rb + b.y + c.y + d.y) * 0.5f;
            e0.w = (rb + b.y - c.y - d.y) * 0.5f;
            e1.x = (ra - b.x + c.x - d.x) * 0.5f;
            e1.y = (ra - b.x - c.x + d.x) * 0.5f;
            e1.z = (rb - b.y + c.y - d.y) * 0.5f;
            e1.w = (rb - b.y - c.y + d.y) * 0.5f;
            int gr = by * TR + 2 * i;
            int gc = bx * TC + 4 * q;
            *reinterpret_cast<float4*>(out + (size_t)gr * NN + gc)       = e0;
            *reinterpret_cast<float4*>(out + (size_t)(gr + 1) * NN + gc) = e1;
        }
    }
}

extern "C" void kernel_launch(void* const* d_in, const int* in_sizes, int n_in,
                              void* d_out, int out_size)
{
    const float* x = (const float*)d_in[0];
    float* out = (float*)d_out;

    pack_weights<<<1, 96>>>((const float*)d_in[1], (const float*)d_in[2],
                            (const float*)d_in[3], (const float*)d_in[4],
                            (const float*)d_in[5], (const float*)d_in[6]);
    void* stage_ptr = nullptr;
    cudaGetSymbolAddress(&stage_ptr, g_wstage);
    cudaMemcpyToSymbolAsync(c_w, stage_ptr, 96 * sizeof(float), 0,
                            cudaMemcpyDeviceToDevice);

    cudaFuncSetAttribute(fused_wavelet_kernel,
                         cudaFuncAttributeMaxDynamicSharedMemorySize, SMEM_BYTES);
    dim3 grid(NN / TC, NN / TR);
    fused_wavelet_kernel<<<grid, 512, SMEM_BYTES>>>(x, out);
}

// round 9
// speedup vs baseline: 2.3571x; 1.0885x over previous
#include <cuda_runtime.h>

#define T   64
#define NN  4096
#define ST1 42   // lvl1 array row stride (40 rows used)

// Shared layout (float offsets).
// LH1/HL1: stored col = logical+4 (cols 0..39). HH1: stored col = logical+5
// (cols 1..40) so conv7 2-col windows start even. Rows: stored = logical+4.
#define O_LH1  0        // 40x42
#define O_HL1  1680
#define O_HH1  3360
#define O_LL2  5040     // 20x20, coords [-2,18), stored = logical+2
#define O_LH2  5440
#define O_HL2  5840
#define O_HH2  6240
#define O_LL3  6640     // 10x10, coords [-1,9)
#define O_LH3  6740
#define O_HL3  6840
#define O_HH3  6940
#define O_CHH2 7040     // 16x16
#define O_CHH1 7296     // 32x32
#define O_REC2 8320     // 16x16
#define SMEM_FLOATS 8576

// Constant weight bank: w7[0..48] w5[49..73] w3[74..82] b7[83] b5[84] b3[85]
__constant__ float c_w[96];
__device__   float g_wstage[96];

#define W7(i) c_w[i]
#define W5(i) c_w[49 + (i)]
#define W3(i) c_w[74 + (i)]
#define B7    c_w[83]
#define B5    c_w[84]
#define B3    c_w[85]

__global__ void pack_weights(const float* __restrict__ w3, const float* __restrict__ b3,
                             const float* __restrict__ w5, const float* __restrict__ b5,
                             const float* __restrict__ w7, const float* __restrict__ b7)
{
    int t = threadIdx.x;
    float v = 0.f;
    if (t < 49)       v = w7[t];
    else if (t < 74)  v = w5[t - 49];
    else if (t < 83)  v = w3[t - 74];
    else if (t == 83) v = b7[0];
    else if (t == 84) v = b5[0];
    else if (t == 85) v = b3[0];
    if (t < 96) g_wstage[t] = v;
}

__global__ __launch_bounds__(512, 4) void fused_wavelet_kernel(
    const float* __restrict__ x, float* __restrict__ out)
{
    __shared__ float s[SMEM_FLOATS];
    const int tid = threadIdx.x;
    const int bx = blockIdx.x, by = blockIdx.y;

    // ---- S1: fused level-1 + level-2 DWT. 400 threads; each owns one lvl2
    //      position = 2x2 lvl1 quads = 4x4 input pixels (4 x float4 from gmem).
    if (tid < 400) {
        int ap = tid / 20, aq = tid - ap * 20;
        int gr = by * T - 8 + 4 * ap;
        int gc = bx * T - 8 + 4 * aq;
        float4 A = make_float4(0.f, 0.f, 0.f, 0.f), B = A, C = A, D = A;
        if ((unsigned)gr < NN && (unsigned)gc < NN) {
            const float* p = x + (size_t)gr * NN + gc;
            A = *reinterpret_cast<const float4*>(p);
            B = *reinterpret_cast<const float4*>(p + NN);
            C = *reinterpret_cast<const float4*>(p + 2 * NN);
            D = *reinterpret_cast<const float4*>(p + 3 * NN);
        }
        float ll00 = (A.x + A.y + B.x + B.y) * 0.5f;
        float lh00 = (A.x + A.y - B.x - B.y) * 0.5f;
        float hl00 = (A.x - A.y + B.x - B.y) * 0.5f;
        float hh00 = (A.x - A.y - B.x + B.y) * 0.5f;
        float ll01 = (A.z + A.w + B.z + B.w) * 0.5f;
        float lh01 = (A.z + A.w - B.z - B.w) * 0.5f;
        float hl01 = (A.z - A.w + B.z - B.w) * 0.5f;
        float hh01 = (A.z - A.w - B.z + B.w) * 0.5f;
        float ll10 = (C.x + C.y + D.x + D.y) * 0.5f;
        float lh10 = (C.x + C.y - D.x - D.y) * 0.5f;
        float hl10 = (C.x - C.y + D.x - D.y) * 0.5f;
        float hh10 = (C.x - C.y - D.x + D.y) * 0.5f;
        float ll11 = (C.z + C.w + D.z + D.w) * 0.5f;
        float lh11 = (C.z + C.w - D.z - D.w) * 0.5f;
        float hl11 = (C.z - C.w + D.z - D.w) * 0.5f;
        float hh11 = (C.z - C.w - D.z + D.w) * 0.5f;

        int r0 = (2 * ap) * ST1 + 2 * aq;
        int r1 = r0 + ST1;
        *reinterpret_cast<float2*>(&s[O_LH1 + r0]) = make_float2(lh00, lh01);
        *reinterpret_cast<float2*>(&s[O_LH1 + r1]) = make_float2(lh10, lh11);
        *reinterpret_cast<float2*>(&s[O_HL1 + r0]) = make_float2(hl00, hl01);
        *reinterpret_cast<float2*>(&s[O_HL1 + r1]) = make_float2(hl10, hl11);
        s[O_HH1 + r0 + 1] = hh00;
        s[O_HH1 + r0 + 2] = hh01;
        s[O_HH1 + r1 + 1] = hh10;
        s[O_HH1 + r1 + 2] = hh11;

        s[O_LL2 + tid] = (ll00 + ll01 + ll10 + ll11) * 0.5f;
        s[O_LH2 + tid] = (ll00 + ll01 - ll10 - ll11) * 0.5f;
        s[O_HL2 + tid] = (ll00 - ll01 + ll10 - ll11) * 0.5f;
        s[O_HH2 + tid] = (ll00 - ll01 - ll10 + ll11) * 0.5f;
    }
    __syncthreads();

    // ---- S2 (one phase, disjoint ranges):
    //   tid 0-127:   conv7 on HH1 -> CHH1. 2 cols x 4 rows per thread.
    //   tid 128-191: conv5 on HH2 -> CHH2. 2 cols x 2 rows per thread.
    //   tid 192-291: level-3 DWT.
    if (tid < 128) {
        int r = tid >> 4;          // 0..7 -> output rows 4r..4r+3
        int c = tid & 15;          // col pair: output cols 2c, 2c+1
        float bv = B7;
        float acc[4][2];
#pragma unroll
        for (int k = 0; k < 4; k++) { acc[k][0] = bv; acc[k][1] = bv; }
#pragma unroll
        for (int u = 0; u < 10; u++) {
            const float* row = &s[O_HH1 + (4 * r + 1 + u) * ST1 + 2 * c + 2];
            float xr[8];
            *reinterpret_cast<float2*>(&xr[0]) = *reinterpret_cast<const float2*>(row);
            *reinterpret_cast<float2*>(&xr[2]) = *reinterpret_cast<const float2*>(row + 2);
            *reinterpret_cast<float2*>(&xr[4]) = *reinterpret_cast<const float2*>(row + 4);
            *reinterpret_cast<float2*>(&xr[6]) = *reinterpret_cast<const float2*>(row + 6);
#pragma unroll
            for (int k = 0; k < 4; k++) {
                int uu = u - k;
                if (uu >= 0 && uu < 7) {
#pragma unroll
                    for (int v = 0; v < 7; v++) {
                        float w = W7(uu * 7 + v);
                        acc[k][0] += xr[v] * w;
                        acc[k][1] += xr[v + 1] * w;
                    }
                }
            }
        }
#pragma unroll
        for (int k = 0; k < 4; k++)
            *reinterpret_cast<float2*>(&s[O_CHH1 + (4 * r + k) * 32 + 2 * c]) =
                make_float2(acc[k][0], acc[k][1]);
    } else if (tid < 192) {
        int t2 = tid - 128;
        int r = t2 >> 3;           // 0..7 -> output rows 2r, 2r+1
        int c = t2 & 7;            // col pair: output cols 2c, 2c+1
        float bv = B5;
        float acc[2][2];
        acc[0][0] = acc[0][1] = acc[1][0] = acc[1][1] = bv;
#pragma unroll
        for (int u = 0; u < 6; u++) {
            const float* row = &s[O_HH2 + (2 * r + u) * 20 + 2 * c];
            float xr[6];
            *reinterpret_cast<float2*>(&xr[0]) = *reinterpret_cast<const float2*>(row);
            *reinterpret_cast<float2*>(&xr[2]) = *reinterpret_cast<const float2*>(row + 2);
            *reinterpret_cast<float2*>(&xr[4]) = *reinterpret_cast<const float2*>(row + 4);
#pragma unroll
            for (int k = 0; k < 2; k++) {
                int uu = u - k;
                if (uu >= 0 && uu < 5) {
#pragma unroll
                    for (int v = 0; v < 5; v++) {
                        float w = W5(uu * 5 + v);
                        acc[k][0] += xr[v] * w;
                        acc[k][1] += xr[v + 1] * w;
                    }
                }
            }
        }
        *reinterpret_cast<float2*>(&s[O_CHH2 + (2 * r) * 16 + 2 * c]) =
            make_float2(acc[0][0], acc[0][1]);
        *reinterpret_cast<float2*>(&s[O_CHH2 + (2 * r + 1) * 16 + 2 * c]) =
            make_float2(acc[1][0], acc[1][1]);
    } else if (tid < 292) {
        int t3 = tid - 192;
        int as = t3 / 10, at = t3 - as * 10;
        float2 t0 = *reinterpret_cast<const float2*>(&s[O_LL2 + (2 * as) * 20 + 2 * at]);
        float2 t1 = *reinterpret_cast<const float2*>(&s[O_LL2 + (2 * as + 1) * 20 + 2 * at]);
        s[O_LL3 + t3] = (t0.x + t0.y + t1.x + t1.y) * 0.5f;
        s[O_LH3 + t3] = (t0.x + t0.y - t1.x - t1.y) * 0.5f;
        s[O_HL3 + t3] = (t0.x - t0.y + t1.x - t1.y) * 0.5f;
        s[O_HH3 + t3] = (t0.x - t0.y - t1.x + t1.y) * 0.5f;
    }
    __syncthreads();

    // ---- S3: IDWT level 3 with inline conv3 (64 threads) -> REC2 (16x16) ----
    if (tid < 64) {
        int i = tid >> 3, j = tid & 7;
        float d = B3;
#pragma unroll
        for (int u = 0; u < 3; u++)
#pragma unroll
            for (int v = 0; v < 3; v++)
                d += s[O_HH3 + (i + u) * 10 + (j + v)] * W3(u * 3 + v);
        float a = s[O_LL3 + (i + 1) * 10 + (j + 1)];
        float b = s[O_LH3 + (i + 1) * 10 + (j + 1)];
        float c = s[O_HL3 + (i + 1) * 10 + (j + 1)];
        *reinterpret_cast<float2*>(&s[O_REC2 + (2 * i) * 16 + 2 * j]) =
            make_float2((a + b + c + d) * 0.5f, (a + b - c - d) * 0.5f);
        *reinterpret_cast<float2*>(&s[O_REC2 + (2 * i + 1) * 16 + 2 * j]) =
            make_float2((a - b + c - d) * 0.5f, (a - b - c + d) * 0.5f);
    }
    __syncthreads();

    // ---- S4: fused IDWT2 + IDWT1 -> global. 256 threads. ----
    if (tid < 256) {
        int p = tid >> 4, q = tid & 15;
        float a2 = s[O_REC2 + tid];
        float b2 = s[O_LH2 + (p + 2) * 20 + (q + 2)];
        float c2 = s[O_HL2 + (p + 2) * 20 + (q + 2)];
        float d2 = s[O_CHH2 + tid];
        float r00 = (a2 + b2 + c2 + d2) * 0.5f;
        float r01 = (a2 + b2 - c2 - d2) * 0.5f;
        float r10 = (a2 - b2 + c2 - d2) * 0.5f;
        float r11 = (a2 - b2 - c2 + d2) * 0.5f;

#pragma unroll
        for (int k = 0; k < 2; k++) {
            int i = 2 * p + k;
            float ra = k ? r10 : r00;
            float rb = k ? r11 : r01;
            float2 b = *reinterpret_cast<const float2*>(&s[O_LH1 + (i + 4) * ST1 + 2 * q + 4]);
            float2 c = *reinterpret_cast<const float2*>(&s[O_HL1 + (i + 4) * ST1 + 2 * q + 4]);
            float2 d = *reinterpret_cast<const float2*>(&s[O_CHH1 + i * 32 + 2 * q]);
            float4 e0, e1;
            e0.x = (ra + b.x + c.x + d.x) * 0.5f;
            e0.y = (ra + b.x - c.x - d.x) * 0.5f;
            e0.z = (rb + b.y + c.y + d.y) * 0.5f;
            e0.w = (rb + b.y - c.y - d.y) * 0.5f;
            e1.x = (ra - b.x + c.x - d.x) * 0.5f;
            e1.y = (ra - b.x - c.x + d.x) * 0.5f;
            e1.z = (rb - b.y + c.y - d.y) * 0.5f;
            e1.w = (rb - b.y - c.y + d.y) * 0.5f;
            int gr = by * T + 2 * i;
            int gc = bx * T + 4 * q;
            *reinterpret_cast<float4*>(out + (size_t)gr * NN + gc)       = e0;
            *reinterpret_cast<float4*>(out + (size_t)(gr + 1) * NN + gc) = e1;
        }
    }
}

extern "C" void kernel_launch(void* const* d_in, const int* in_sizes, int n_in,
                              void* d_out, int out_size)
{
    const float* x = (const float*)d_in[0];
    float* out = (float*)d_out;

    pack_weights<<<1, 96>>>((const float*)d_in[1], (const float*)d_in[2],
                            (const float*)d_in[3], (const float*)d_in[4],
                            (const float*)d_in[5], (const float*)d_in[6]);
    void* stage_ptr = nullptr;
    cudaGetSymbolAddress(&stage_ptr, g_wstage);
    cudaMemcpyToSymbolAsync(c_w, stage_ptr, 96 * sizeof(float), 0,
                            cudaMemcpyDeviceToDevice);

    dim3 grid(NN / T, NN / T);
    fused_wavelet_kernel<<<grid, 512>>>(x, out);
}